// round 9
// baseline (speedup 1.0000x reference)
#include <cuda_runtime.h>
#include <cuda_fp16.h>
#include <math.h>
#include <stdint.h>

// Fixed shapes: N=4096 tokens, C=1024, I=2048, E=8.
#define MAX_N 4096
#define MAX_C 1024
#define MAX_I 2048
#define MAX_E 8

// ---------------- device scratch ----------------
__device__ __align__(256) __half g_h_h[(size_t)MAX_N * MAX_C];                 // fp16 H
__device__ __align__(256) __half g_inter_h[(size_t)MAX_E * MAX_N * MAX_I];     // fp16 inter (compact)
__device__ __align__(256) __half g_w1t[(size_t)MAX_E * MAX_I * MAX_C];         // [E][I][C]
__device__ __align__(256) __half g_w2t[(size_t)MAX_E * MAX_C * MAX_I];         // [E][C][I]
__device__ __align__(256) float g_part[(size_t)MAX_E * MAX_N * MAX_C];         // compact rows
__device__ __align__(256) float g_scale[(size_t)MAX_N * MAX_E];
__device__ __align__(256) int   g_tok[(size_t)MAX_E * MAX_N];
__device__ __align__(256) int   g_pos[(size_t)MAX_N * MAX_E];
__device__ int   g_cnt[MAX_E];
__device__ float g_prec[MAX_E + 1];

#define L2_EPS 1e-12f

// ---------------- PTX helpers (baseline sm_80+ features only) ----------------
__device__ __forceinline__ uint32_t smem_to_u32(const void* p) {
    uint32_t a;
    asm("{ .reg .u64 t; cvta.to.shared.u64 t, %1; cvt.u32.u64 %0, t; }" : "=r"(a) : "l"(p));
    return a;
}
#define CP_ASYNC16(s, g) \
    asm volatile("cp.async.cg.shared.global [%0], [%1], 16;" :: "r"(s), "l"(g))
#define CP_COMMIT() asm volatile("cp.async.commit_group;" ::: "memory")
#define CP_WAIT0()  asm volatile("cp.async.wait_group 0;" ::: "memory")
#define CP_WAIT1()  asm volatile("cp.async.wait_group 1;" ::: "memory")
#define CP_WAIT2()  asm volatile("cp.async.wait_group 2;" ::: "memory")
#define LDSM4(R, addr) \
    asm volatile("ldmatrix.sync.aligned.m8n8.x4.shared.b16 {%0,%1,%2,%3}, [%4];" \
        : "=r"((R)[0]), "=r"((R)[1]), "=r"((R)[2]), "=r"((R)[3]) : "r"(addr))
#define LDSM2(R, addr) \
    asm volatile("ldmatrix.sync.aligned.m8n8.x2.shared.b16 {%0,%1}, [%2];" \
        : "=r"((R)[0]), "=r"((R)[1]) : "r"(addr))
#define MMA16816F16(Cc, A, B) \
    asm volatile("mma.sync.aligned.m16n8k16.row.col.f32.f16.f16.f32 " \
        "{%0,%1,%2,%3}, {%4,%5,%6,%7}, {%8,%9}, {%0,%1,%2,%3};" \
        : "+f"((Cc)[0]), "+f"((Cc)[1]), "+f"((Cc)[2]), "+f"((Cc)[3]) \
        : "r"((A)[0]), "r"((A)[1]), "r"((A)[2]), "r"((A)[3]), "r"((B)[0]), "r"((B)[1]))

// ---------------- prep: sim col norms + logit scale + zero counters ----------------
__global__ void prec_kernel(const float* __restrict__ sim, const float* __restrict__ temp,
                            int C, int E) {
    int w = threadIdx.x >> 5, lane = threadIdx.x & 31;
    if (w < E) {
        float s = 0.f;
        for (int c = lane; c < C; c += 32) { float v = sim[(size_t)c * E + w]; s += v * v; }
        #pragma unroll
        for (int o = 16; o > 0; o >>= 1) s += __shfl_xor_sync(0xffffffffu, s, o);
        if (lane == 0) g_prec[w] = 1.f / fmaxf(sqrtf(s), L2_EPS);
    }
    if (threadIdx.x == 0) g_prec[MAX_E] = 1.f / (1.f + expf(-temp[0]));
    if (threadIdx.x < MAX_E) g_cnt[threadIdx.x] = 0;
}

// ---------------- gating (exact fp32) + fused compaction ----------------
__global__ void gating_kernel(const float* __restrict__ h, const float* __restrict__ sim,
                              const float* __restrict__ gates, const float* __restrict__ mask,
                              const int* __restrict__ min_experts_p,
                              float* __restrict__ out_logits, float* __restrict__ out_act,
                              int C, int E) {
    const int n = blockIdx.x, tid = threadIdx.x;
    float hh = 0.f;
    float dot[MAX_E];
    #pragma unroll
    for (int e = 0; e < MAX_E; e++) dot[e] = 0.f;
    const float* hrow = h + (size_t)n * C;
    for (int c = tid; c < C; c += 128) {
        float v = hrow[c];
        hh += v * v;
        const float* srow = sim + (size_t)c * E;
        #pragma unroll
        for (int e = 0; e < MAX_E; e++) if (e < E) dot[e] += v * srow[e];
    }
    __shared__ float sd[(MAX_E + 1) * 128];
    sd[tid] = hh;
    #pragma unroll
    for (int e = 0; e < MAX_E; e++) if (e < E) sd[(e + 1) * 128 + tid] = dot[e];
    __syncthreads();
    for (int s = 64; s > 0; s >>= 1) {
        if (tid < s)
            for (int r = 0; r <= E; r++) sd[r * 128 + tid] += sd[r * 128 + tid + s];
        __syncthreads();
    }
    if (tid == 0) {
        float inv_h = 1.f / fmaxf(sqrtf(sd[0]), L2_EPS);
        float ls = g_prec[MAX_E];
        float logits[MAX_E], act[MAX_E];
        float suma = 0.f;
        for (int e = 0; e < E; e++) {
            float lg = sd[(e + 1) * 128] * inv_h * g_prec[e];
            lg *= mask[e];
            logits[e] = lg;
            float gated = lg - gates[e] * ls;
            float a = (gated > 0.f) ? 1.f : 0.f;
            act[e] = a; suma += a;
        }
        if (suma == 0.f) {
            int k = min_experts_p ? *min_experts_p : 2;
            if (k <= 0 || k > E) {
                float f = __int_as_float(k);
                int k2 = (int)f;
                k = (k2 > 0 && k2 <= E) ? k2 : 2;
            }
            bool chosen[MAX_E];
            for (int e = 0; e < E; e++) chosen[e] = false;
            for (int j = 0; j < k; j++) {
                int best = -1; float bv = -1e30f;
                for (int e = 0; e < E; e++)
                    if (!chosen[e] && logits[e] > bv) { bv = logits[e]; best = e; }
                if (best >= 0) { chosen[best] = true; act[best] = 1.f; suma += 1.f; }
            }
        }
        float num = fmaxf(suma, 1.f);
        for (int e = 0; e < E; e++) {
            out_logits[(size_t)n * E + e] = logits[e];
            out_act[(size_t)n * E + e] = act[e];
            float sc = act[e] / num;
            g_scale[(size_t)n * E + e] = sc;
            if (sc != 0.f) {                       // fused compaction
                int slot = atomicAdd(&g_cnt[e], 1);
                g_tok[(size_t)e * MAX_N + slot] = n;
                g_pos[(size_t)n * E + e] = slot;
            }
        }
    }
}

// ---------------- fused prep: H -> fp16; W1, W2 -> transposed fp16 ----------------
__global__ void prep_kernel(const float* __restrict__ h,
                            const float* __restrict__ w1, const float* __restrict__ w2,
                            int N, int C, int I, int nb_h, int nb_w1) {
    __shared__ float t[32][33];
    const int bid = blockIdx.x;
    const int tid = threadIdx.x;

    if (bid < nb_h) {
        int i4 = bid * 256 + tid;
        float4 v = ((const float4*)h)[i4];
        __half h0 = __float2half_rn(v.x), h1 = __float2half_rn(v.y);
        __half h2 = __float2half_rn(v.z), h3 = __float2half_rn(v.w);
        uint2 hp;
        hp.x = (uint32_t)__half_as_ushort(h0) | ((uint32_t)__half_as_ushort(h1) << 16);
        hp.y = (uint32_t)__half_as_ushort(h2) | ((uint32_t)__half_as_ushort(h3) << 16);
        ((uint2*)g_h_h)[i4] = hp;
        return;
    }

    const float* src;
    __half* oh;
    int R, Cc, bx, by, e;
    if (bid < nb_h + nb_w1) {
        int b = bid - nb_h;
        R = C; Cc = I;                       // w1: [C][I] per expert
        int per_e = (Cc / 32) * (R / 32);
        e = b / per_e;
        int rem = b % per_e;
        bx = rem % (Cc / 32); by = rem / (Cc / 32);
        src = w1 + (size_t)e * R * Cc;
        oh = g_w1t + (size_t)e * R * Cc;
    } else {
        int b = bid - nb_h - nb_w1;
        R = I; Cc = C;                       // w2: [I][C] per expert
        int per_e = (Cc / 32) * (R / 32);
        e = b / per_e;
        int rem = b % per_e;
        bx = rem % (Cc / 32); by = rem / (Cc / 32);
        src = w2 + (size_t)e * R * Cc;
        oh = g_w2t + (size_t)e * R * Cc;
    }
    const int tx = tid & 31, ty = tid >> 5;  // (32, 8)
    int cbase = bx * 32, rbase = by * 32;
    #pragma unroll
    for (int i = 0; i < 4; i++) {
        int r = rbase + ty + i * 8;
        t[ty + i * 8][tx] = src[(size_t)r * Cc + cbase + tx];
    }
    __syncthreads();
    #pragma unroll
    for (int i = 0; i < 4; i++) {
        int n = cbase + ty + i * 8;
        int k = rbase + tx;
        oh[(size_t)n * R + k] = __float2half_rn(t[tx][ty + i * 8]);
    }
}

// ---------------- HMMA fp16 GEMM, CTA tile 128(M) x 256(N), warp tile 64x64 ----------------
// D = A_fp16 @ B_fp16^T, fp32 accumulate. 8 warps: wm in {0,1}, wn in {0..3}.
// MODE 0: inter[e][slot] = gelu(H[tok[e][slot]] @ W1t[e]^T)  K=C, ncols=I (A gathered)
// MODE 1: part[e][slot]  = inter[e][slot] @ W2t[e]^T         K=I, ncols=C (A compact)
// Stage: A 128x32 fp16 (10240 B padded) + B 256x32 fp16 (20480 B padded) = 30720 B; 3 stages.
static constexpr int STAGE_BYTES = 30720;
static constexpr int SMEM_GEMM = 3 * STAGE_BYTES;   // 92160 B

template <int MODE>
__global__ __launch_bounds__(256)
void mma_gemm(int K, int ncols) {
    extern __shared__ __align__(128) char smem[];
    const int tid = threadIdx.x;
    const int wid = tid >> 5, lane = tid & 31;
    const int e = blockIdx.z;
    const int m0 = blockIdx.y * 128, n0 = blockIdx.x * 256;
    const int wm = wid & 1, wn = wid >> 1;

    const int cnt = g_cnt[e];
    if (m0 >= cnt) return;

    const __half* A = (MODE == 0) ? g_h_h : g_inter_h + (size_t)e * MAX_N * MAX_I;
    const __half* B = ((MODE == 0) ? g_w1t : g_w2t) + (size_t)e * ncols * K + (size_t)n0 * K;

    // Per-thread A row indices for the two copy rows it owns (r0 and r0+64).
    const int r0 = tid >> 2;
    int ga0, ga1;
    if (MODE == 0) {
        const int* tk = g_tok + (size_t)e * MAX_N;
        ga0 = tk[min(m0 + r0, cnt - 1)];
        ga1 = tk[min(m0 + r0 + 64, cnt - 1)];
    } else {
        ga0 = min(m0 + r0, cnt - 1);
        ga1 = min(m0 + r0 + 64, cnt - 1);
    }
    const int c16 = (tid & 3);

    const uint32_t sb = smem_to_u32(smem);

    auto load_stage = [&](int buf, int k0) {
        uint32_t base = sb + (uint32_t)buf * (uint32_t)STAGE_BYTES;
        uint32_t soff = (uint32_t)r0 * 80u + (uint32_t)c16 * 16u;
        // A: 128 rows, 2 per thread
        CP_ASYNC16(base + soff,                A + (size_t)ga0 * K + k0 + c16 * 8);
        CP_ASYNC16(base + 64u * 80u + soff,    A + (size_t)ga1 * K + k0 + c16 * 8);
        // B: 256 rows, 4 per thread
        #pragma unroll
        for (int i = 0; i < 4; i++) {
            int row = r0 + i * 64;
            CP_ASYNC16(base + 10240u + (uint32_t)row * 80u + (uint32_t)c16 * 16u,
                       B + (size_t)row * K + k0 + c16 * 8);
        }
        CP_COMMIT();
    };

    const int NC = K >> 5;   // >= 32
    load_stage(0, 0);
    load_stage(1, 32);
    load_stage(2, 64);

    float acc[4][8][4];
    #pragma unroll
    for (int a = 0; a < 4; a++)
        #pragma unroll
        for (int b = 0; b < 8; b++)
            #pragma unroll
            for (int d = 0; d < 4; d++) acc[a][b][d] = 0.f;

    int buf = 0;
    for (int c = 0; c < NC; c++) {
        if (c + 2 < NC)      { CP_WAIT2(); }
        else if (c + 1 < NC) { CP_WAIT1(); }
        else                 { CP_WAIT0(); }
        __syncthreads();
        uint32_t base = sb + (uint32_t)buf * (uint32_t)STAGE_BYTES;

        #pragma unroll
        for (int ks = 0; ks < 2; ks++) {
            uint32_t Af[4][4], Bf[8][2];
            int arow = wm * 64 + (lane & 15);
            int acolb = (ks * 16 + (lane >> 4) * 8) * 2;
            #pragma unroll
            for (int mt = 0; mt < 4; mt++) {
                uint32_t ad = base + (uint32_t)(arow + mt * 16) * 80u + (uint32_t)acolb;
                LDSM4(Af[mt], ad);
            }
            int brow = wn * 64 + (lane & 7);
            int bkb = (ks * 16 + ((lane >> 3) & 1) * 8) * 2;
            #pragma unroll
            for (int nt = 0; nt < 8; nt++) {
                uint32_t bd = base + 10240u + (uint32_t)(brow + nt * 8) * 80u + (uint32_t)bkb;
                LDSM2(Bf[nt], bd);
            }
            #pragma unroll
            for (int mt = 0; mt < 4; mt++)
                #pragma unroll
                for (int nt = 0; nt < 8; nt++)
                    MMA16816F16(acc[mt][nt], Af[mt], Bf[nt]);
        }
        __syncthreads();
        if (c + 3 < NC) load_stage(buf, (c + 3) * 32);
        buf = (buf == 2) ? 0 : buf + 1;
    }

    // ---------------- epilogue (compact rows, guarded by cnt) ----------------
    const int gq = lane >> 2, t2 = (lane & 3) * 2;
    if (MODE == 0) {
        __half* oh = g_inter_h + (size_t)e * MAX_N * MAX_I;
        #pragma unroll
        for (int mt = 0; mt < 4; mt++) {
            #pragma unroll
            for (int nt = 0; nt < 8; nt++) {
                int col = n0 + wn * 64 + nt * 8 + t2;
                #pragma unroll
                for (int hf = 0; hf < 2; hf++) {
                    int row = m0 + wm * 64 + mt * 16 + gq + hf * 8;
                    if (row >= cnt) continue;
                    float x0 = acc[mt][nt][2 * hf];
                    float x1 = acc[mt][nt][2 * hf + 1];
                    float g0 = 0.5f * x0 * (1.f + erff(x0 * 0.70710678118654752f));
                    float g1 = 0.5f * x1 * (1.f + erff(x1 * 0.70710678118654752f));
                    __half h0 = __float2half_rn(g0);
                    __half h1 = __float2half_rn(g1);
                    uint32_t hp = (uint32_t)__half_as_ushort(h0) |
                                  ((uint32_t)__half_as_ushort(h1) << 16);
                    *(uint32_t*)(oh + (size_t)row * ncols + col) = hp;
                }
            }
        }
    } else {
        float* op = g_part + (size_t)e * MAX_N * MAX_C;
        #pragma unroll
        for (int mt = 0; mt < 4; mt++) {
            #pragma unroll
            for (int nt = 0; nt < 8; nt++) {
                int col = n0 + wn * 64 + nt * 8 + t2;
                #pragma unroll
                for (int hf = 0; hf < 2; hf++) {
                    int row = m0 + wm * 64 + mt * 16 + gq + hf * 8;
                    if (row >= cnt) continue;
                    float2 v = make_float2(acc[mt][nt][2 * hf], acc[mt][nt][2 * hf + 1]);
                    *(float2*)(op + (size_t)row * ncols + col) = v;
                }
            }
        }
    }
}

// ---------------- reduce: final[n] = sum_e scale[n][e] * part[e][pos[n][e]] ----------------
__global__ void reduce_kernel(float* __restrict__ out, int N, int C, int E) {
    int i = blockIdx.x * blockDim.x + threadIdx.x;
    int per_row = C / 4;
    if (i >= N * per_row) return;
    int n = i / per_row, c4 = i % per_row;
    float4 acc = make_float4(0.f, 0.f, 0.f, 0.f);
    const float* sr = g_scale + (size_t)n * E;
    const int* pr = g_pos + (size_t)n * E;
    for (int e = 0; e < E; e++) {
        float s = sr[e];
        if (s != 0.f) {
            int p = pr[e];
            float4 v = ((const float4*)(g_part + (size_t)e * MAX_N * MAX_C + (size_t)p * C))[c4];
            acc.x += s * v.x; acc.y += s * v.y; acc.z += s * v.z; acc.w += s * v.w;
        }
    }
    ((float4*)(out + (size_t)n * C))[c4] = acc;
}

// ---------------- launch ----------------
extern "C" void kernel_launch(void* const* d_in, const int* in_sizes, int n_in,
                              void* d_out, int out_size) {
    const float* h     = (const float*)d_in[0];
    const float* sim   = (const float*)d_in[1];
    const float* gates = (const float*)d_in[2];
    const float* temp  = (const float*)d_in[3];
    const float* mask  = (const float*)d_in[4];
    const float* w1    = (const float*)d_in[5];
    const float* w2    = (const float*)d_in[6];
    const int*   mi    = (const int*)d_in[7];

    const int E = in_sizes[2];
    const int C = in_sizes[1] / E;
    const int I = in_sizes[5] / (E * C);
    const int N = in_sizes[0] / C;

    float* out_final  = (float*)d_out;
    float* out_logits = out_final + (size_t)N * C;
    float* out_act    = out_logits + (size_t)N * E;

    cudaFuncSetAttribute(mma_gemm<0>, cudaFuncAttributeMaxDynamicSharedMemorySize, SMEM_GEMM);
    cudaFuncSetAttribute(mma_gemm<1>, cudaFuncAttributeMaxDynamicSharedMemorySize, SMEM_GEMM);

    prec_kernel<<<1, 256>>>(sim, temp, C, E);
    gating_kernel<<<N, 128>>>(h, sim, gates, mask, mi, out_logits, out_act, C, E);

    int nb_h  = (N * C) / 1024;            // split_h blocks (256 thr x 4 elems)
    int nb_w1 = E * (C / 32) * (I / 32);
    int nb_w2 = E * (I / 32) * (C / 32);
    prep_kernel<<<nb_h + nb_w1 + nb_w2, 256>>>(h, w1, w2, N, C, I, nb_h, nb_w1);

    mma_gemm<0><<<dim3(I / 256, N / 128, E), 256, SMEM_GEMM>>>(C, I);
    mma_gemm<1><<<dim3(C / 256, N / 128, E), 256, SMEM_GEMM>>>(I, C);

    int rthreads = N * (C / 4);
    reduce_kernel<<<(rthreads + 255) / 256, 256>>>(out_final, N, C, E);
}

// round 10
// speedup vs baseline: 1.1447x; 1.1447x over previous
#include <cuda_runtime.h>
#include <cuda_fp16.h>
#include <math.h>
#include <stdint.h>

// Fixed shapes: N=4096 tokens, C=1024, I=2048, E=8.
#define MAX_N 4096
#define MAX_C 1024
#define MAX_I 2048
#define MAX_E 8

// ---------------- device scratch ----------------
__device__ __align__(256) __half g_h_h[(size_t)MAX_N * MAX_C];                 // fp16 H
__device__ __align__(256) __half g_inter_h[(size_t)MAX_E * MAX_N * MAX_I];     // fp16 inter (compact)
__device__ __align__(256) __half g_w1t[(size_t)MAX_E * MAX_I * MAX_C];         // [E][I][C]
__device__ __align__(256) __half g_w2t[(size_t)MAX_E * MAX_C * MAX_I];         // [E][C][I]
__device__ __align__(256) float g_part[(size_t)MAX_E * MAX_N * MAX_C];         // compact rows
__device__ __align__(256) float g_scale[(size_t)MAX_N * MAX_E];
__device__ __align__(256) int   g_tok[(size_t)MAX_E * MAX_N];
__device__ __align__(256) int   g_pos[(size_t)MAX_N * MAX_E];
__device__ int   g_cnt[MAX_E];
__device__ float g_prec[MAX_E + 1];

#define L2_EPS 1e-12f

// ---------------- PTX helpers (baseline sm_80+ features only) ----------------
__device__ __forceinline__ uint32_t smem_to_u32(const void* p) {
    uint32_t a;
    asm("{ .reg .u64 t; cvta.to.shared.u64 t, %1; cvt.u32.u64 %0, t; }" : "=r"(a) : "l"(p));
    return a;
}
#define CP_ASYNC16(s, g) \
    asm volatile("cp.async.cg.shared.global [%0], [%1], 16;" :: "r"(s), "l"(g))
#define CP_COMMIT() asm volatile("cp.async.commit_group;" ::: "memory")
#define CP_WAIT0()  asm volatile("cp.async.wait_group 0;" ::: "memory")
#define CP_WAIT1()  asm volatile("cp.async.wait_group 1;" ::: "memory")
#define LDSM4(R, addr) \
    asm volatile("ldmatrix.sync.aligned.m8n8.x4.shared.b16 {%0,%1,%2,%3}, [%4];" \
        : "=r"((R)[0]), "=r"((R)[1]), "=r"((R)[2]), "=r"((R)[3]) : "r"(addr))
#define LDSM2(R, addr) \
    asm volatile("ldmatrix.sync.aligned.m8n8.x2.shared.b16 {%0,%1}, [%2];" \
        : "=r"((R)[0]), "=r"((R)[1]) : "r"(addr))
#define MMA16816F16(Cc, A, B) \
    asm volatile("mma.sync.aligned.m16n8k16.row.col.f32.f16.f16.f32 " \
        "{%0,%1,%2,%3}, {%4,%5,%6,%7}, {%8,%9}, {%0,%1,%2,%3};" \
        : "+f"((Cc)[0]), "+f"((Cc)[1]), "+f"((Cc)[2]), "+f"((Cc)[3]) \
        : "r"((A)[0]), "r"((A)[1]), "r"((A)[2]), "r"((A)[3]), "r"((B)[0]), "r"((B)[1]))

// ---------------- prep: sim col norms + logit scale + zero counters ----------------
__global__ void prec_kernel(const float* __restrict__ sim, const float* __restrict__ temp,
                            int C, int E) {
    int w = threadIdx.x >> 5, lane = threadIdx.x & 31;
    if (w < E) {
        float s = 0.f;
        for (int c = lane; c < C; c += 32) { float v = sim[(size_t)c * E + w]; s += v * v; }
        #pragma unroll
        for (int o = 16; o > 0; o >>= 1) s += __shfl_xor_sync(0xffffffffu, s, o);
        if (lane == 0) g_prec[w] = 1.f / fmaxf(sqrtf(s), L2_EPS);
    }
    if (threadIdx.x == 0) g_prec[MAX_E] = 1.f / (1.f + expf(-temp[0]));
    if (threadIdx.x < MAX_E) g_cnt[threadIdx.x] = 0;
}

// ---------------- gating (exact fp32) + fused compaction ----------------
__global__ void gating_kernel(const float* __restrict__ h, const float* __restrict__ sim,
                              const float* __restrict__ gates, const float* __restrict__ mask,
                              const int* __restrict__ min_experts_p,
                              float* __restrict__ out_logits, float* __restrict__ out_act,
                              int C, int E) {
    const int n = blockIdx.x, tid = threadIdx.x;
    float hh = 0.f;
    float dot[MAX_E];
    #pragma unroll
    for (int e = 0; e < MAX_E; e++) dot[e] = 0.f;
    const float* hrow = h + (size_t)n * C;
    for (int c = tid; c < C; c += 128) {
        float v = hrow[c];
        hh += v * v;
        const float* srow = sim + (size_t)c * E;
        #pragma unroll
        for (int e = 0; e < MAX_E; e++) if (e < E) dot[e] += v * srow[e];
    }
    __shared__ float sd[(MAX_E + 1) * 128];
    sd[tid] = hh;
    #pragma unroll
    for (int e = 0; e < MAX_E; e++) if (e < E) sd[(e + 1) * 128 + tid] = dot[e];
    __syncthreads();
    for (int s = 64; s > 0; s >>= 1) {
        if (tid < s)
            for (int r = 0; r <= E; r++) sd[r * 128 + tid] += sd[r * 128 + tid + s];
        __syncthreads();
    }
    if (tid == 0) {
        float inv_h = 1.f / fmaxf(sqrtf(sd[0]), L2_EPS);
        float ls = g_prec[MAX_E];
        float logits[MAX_E], act[MAX_E];
        float suma = 0.f;
        for (int e = 0; e < E; e++) {
            float lg = sd[(e + 1) * 128] * inv_h * g_prec[e];
            lg *= mask[e];
            logits[e] = lg;
            float gated = lg - gates[e] * ls;
            float a = (gated > 0.f) ? 1.f : 0.f;
            act[e] = a; suma += a;
        }
        if (suma == 0.f) {
            int k = min_experts_p ? *min_experts_p : 2;
            if (k <= 0 || k > E) {
                float f = __int_as_float(k);
                int k2 = (int)f;
                k = (k2 > 0 && k2 <= E) ? k2 : 2;
            }
            bool chosen[MAX_E];
            for (int e = 0; e < E; e++) chosen[e] = false;
            for (int j = 0; j < k; j++) {
                int best = -1; float bv = -1e30f;
                for (int e = 0; e < E; e++)
                    if (!chosen[e] && logits[e] > bv) { bv = logits[e]; best = e; }
                if (best >= 0) { chosen[best] = true; act[best] = 1.f; suma += 1.f; }
            }
        }
        float num = fmaxf(suma, 1.f);
        for (int e = 0; e < E; e++) {
            out_logits[(size_t)n * E + e] = logits[e];
            out_act[(size_t)n * E + e] = act[e];
            float sc = act[e] / num;
            g_scale[(size_t)n * E + e] = sc;
            if (sc != 0.f) {                       // fused compaction
                int slot = atomicAdd(&g_cnt[e], 1);
                g_tok[(size_t)e * MAX_N + slot] = n;
                g_pos[(size_t)n * E + e] = slot;
            }
        }
    }
}

// ---------------- fused prep: H -> fp16; W1, W2 -> transposed fp16 ----------------
__global__ void prep_kernel(const float* __restrict__ h,
                            const float* __restrict__ w1, const float* __restrict__ w2,
                            int N, int C, int I, int nb_h, int nb_w1) {
    __shared__ float t[32][33];
    const int bid = blockIdx.x;
    const int tid = threadIdx.x;

    if (bid < nb_h) {
        int i4 = bid * 256 + tid;
        float4 v = ((const float4*)h)[i4];
        __half h0 = __float2half_rn(v.x), h1 = __float2half_rn(v.y);
        __half h2 = __float2half_rn(v.z), h3 = __float2half_rn(v.w);
        uint2 hp;
        hp.x = (uint32_t)__half_as_ushort(h0) | ((uint32_t)__half_as_ushort(h1) << 16);
        hp.y = (uint32_t)__half_as_ushort(h2) | ((uint32_t)__half_as_ushort(h3) << 16);
        ((uint2*)g_h_h)[i4] = hp;
        return;
    }

    const float* src;
    __half* oh;
    int R, Cc, bx, by, e;
    if (bid < nb_h + nb_w1) {
        int b = bid - nb_h;
        R = C; Cc = I;                       // w1: [C][I] per expert
        int per_e = (Cc / 32) * (R / 32);
        e = b / per_e;
        int rem = b % per_e;
        bx = rem % (Cc / 32); by = rem / (Cc / 32);
        src = w1 + (size_t)e * R * Cc;
        oh = g_w1t + (size_t)e * R * Cc;
    } else {
        int b = bid - nb_h - nb_w1;
        R = I; Cc = C;                       // w2: [I][C] per expert
        int per_e = (Cc / 32) * (R / 32);
        e = b / per_e;
        int rem = b % per_e;
        bx = rem % (Cc / 32); by = rem / (Cc / 32);
        src = w2 + (size_t)e * R * Cc;
        oh = g_w2t + (size_t)e * R * Cc;
    }
    const int tx = tid & 31, ty = tid >> 5;  // (32, 8)
    int cbase = bx * 32, rbase = by * 32;
    #pragma unroll
    for (int i = 0; i < 4; i++) {
        int r = rbase + ty + i * 8;
        t[ty + i * 8][tx] = src[(size_t)r * Cc + cbase + tx];
    }
    __syncthreads();
    #pragma unroll
    for (int i = 0; i < 4; i++) {
        int n = cbase + ty + i * 8;
        int k = rbase + tx;
        oh[(size_t)n * R + k] = __float2half_rn(t[tx][ty + i * 8]);
    }
}

// ---------------- HMMA fp16 GEMM, CTA tile 128x128, 4 warps of 64x64 ----------------
// 128 threads/CTA -> ~164 regs -> 3 CTAs/SM (independent barrier domains overlap).
// MODE 0: inter[e][slot] = gelu(H[tok[e][slot]] @ W1t[e]^T)  K=C, ncols=I (A gathered)
// MODE 1: part[e][slot]  = inter[e][slot] @ W2t[e]^T         K=I, ncols=C (A compact)
// Stage: A 128x32 fp16 (10240 B padded) + B 128x32 fp16 (10240 B padded) = 20480 B; 2 stages.
static constexpr int STAGE_BYTES = 20480;
static constexpr int SMEM_GEMM = 2 * STAGE_BYTES;   // 40960 B

template <int MODE>
__global__ __launch_bounds__(128)
void mma_gemm(int K, int ncols) {
    extern __shared__ __align__(128) char smem[];
    const int tid = threadIdx.x;
    const int wid = tid >> 5, lane = tid & 31;
    const int e = blockIdx.z;
    const int m0 = blockIdx.y * 128, n0 = blockIdx.x * 128;
    const int wm = wid & 1, wn = (wid >> 1) & 1;   // 2x2 warp grid, 64x64 each

    const int cnt = g_cnt[e];
    if (m0 >= cnt) return;

    const __half* A = (MODE == 0) ? g_h_h : g_inter_h + (size_t)e * MAX_N * MAX_I;
    const __half* B = ((MODE == 0) ? g_w1t : g_w2t) + (size_t)e * ncols * K + (size_t)n0 * K;

    // Copy plan: 128 rows x 4 chunks(16B); 128 threads -> 4 (row,chunk) tasks each
    // task i: row = (tid>>2) + 32*i, chunk = tid&3
    const int r4 = tid >> 2;
    const int c16 = tid & 3;
    int ga[4];
    #pragma unroll
    for (int i = 0; i < 4; i++) {
        int row = r4 + 32 * i;
        if (MODE == 0) {
            const int* tk = g_tok + (size_t)e * MAX_N;
            ga[i] = tk[min(m0 + row, cnt - 1)];
        } else {
            ga[i] = min(m0 + row, cnt - 1);
        }
    }

    const uint32_t sb = smem_to_u32(smem);

    auto load_stage = [&](int buf, int k0) {
        uint32_t base = sb + (uint32_t)buf * (uint32_t)STAGE_BYTES;
        #pragma unroll
        for (int i = 0; i < 4; i++) {
            int row = r4 + 32 * i;
            uint32_t soff = (uint32_t)row * 80u + (uint32_t)c16 * 16u;
            CP_ASYNC16(base + soff,           A + (size_t)ga[i] * K + k0 + c16 * 8);
            CP_ASYNC16(base + 10240u + soff,  B + (size_t)row * K + k0 + c16 * 8);
        }
        CP_COMMIT();
    };

    const int NC = K >> 5;   // >= 32
    load_stage(0, 0);
    load_stage(1, 32);

    float acc[4][8][4];
    #pragma unroll
    for (int a = 0; a < 4; a++)
        #pragma unroll
        for (int b = 0; b < 8; b++)
            #pragma unroll
            for (int d = 0; d < 4; d++) acc[a][b][d] = 0.f;

    for (int c = 0; c < NC; c++) {
        if (c == NC - 1) { CP_WAIT0(); } else { CP_WAIT1(); }
        __syncthreads();
        uint32_t base = sb + (uint32_t)(c & 1) * (uint32_t)STAGE_BYTES;

        #pragma unroll
        for (int ks = 0; ks < 2; ks++) {
            uint32_t Af[4][4], Bf[8][2];
            int arow = wm * 64 + (lane & 15);
            int acolb = (ks * 16 + (lane >> 4) * 8) * 2;
            #pragma unroll
            for (int mt = 0; mt < 4; mt++) {
                uint32_t ad = base + (uint32_t)(arow + mt * 16) * 80u + (uint32_t)acolb;
                LDSM4(Af[mt], ad);
            }
            int brow = wn * 64 + (lane & 7);
            int bkb = (ks * 16 + ((lane >> 3) & 1) * 8) * 2;
            #pragma unroll
            for (int nt = 0; nt < 8; nt++) {
                uint32_t bd = base + 10240u + (uint32_t)(brow + nt * 8) * 80u + (uint32_t)bkb;
                LDSM2(Bf[nt], bd);
            }
            #pragma unroll
            for (int mt = 0; mt < 4; mt++)
                #pragma unroll
                for (int nt = 0; nt < 8; nt++)
                    MMA16816F16(acc[mt][nt], Af[mt], Bf[nt]);
        }
        __syncthreads();
        if (c + 2 < NC) load_stage(c & 1, (c + 2) * 32);
    }

    // ---------------- epilogue (compact rows, guarded by cnt) ----------------
    const int gq = lane >> 2, t2 = (lane & 3) * 2;
    if (MODE == 0) {
        __half* oh = g_inter_h + (size_t)e * MAX_N * MAX_I;
        #pragma unroll
        for (int mt = 0; mt < 4; mt++) {
            #pragma unroll
            for (int nt = 0; nt < 8; nt++) {
                int col = n0 + wn * 64 + nt * 8 + t2;
                #pragma unroll
                for (int hf = 0; hf < 2; hf++) {
                    int row = m0 + wm * 64 + mt * 16 + gq + hf * 8;
                    if (row >= cnt) continue;
                    float x0 = acc[mt][nt][2 * hf];
                    float x1 = acc[mt][nt][2 * hf + 1];
                    float g0 = 0.5f * x0 * (1.f + erff(x0 * 0.70710678118654752f));
                    float g1 = 0.5f * x1 * (1.f + erff(x1 * 0.70710678118654752f));
                    __half h0 = __float2half_rn(g0);
                    __half h1 = __float2half_rn(g1);
                    uint32_t hp = (uint32_t)__half_as_ushort(h0) |
                                  ((uint32_t)__half_as_ushort(h1) << 16);
                    *(uint32_t*)(oh + (size_t)row * ncols + col) = hp;
                }
            }
        }
    } else {
        float* op = g_part + (size_t)e * MAX_N * MAX_C;
        #pragma unroll
        for (int mt = 0; mt < 4; mt++) {
            #pragma unroll
            for (int nt = 0; nt < 8; nt++) {
                int col = n0 + wn * 64 + nt * 8 + t2;
                #pragma unroll
                for (int hf = 0; hf < 2; hf++) {
                    int row = m0 + wm * 64 + mt * 16 + gq + hf * 8;
                    if (row >= cnt) continue;
                    float2 v = make_float2(acc[mt][nt][2 * hf], acc[mt][nt][2 * hf + 1]);
                    *(float2*)(op + (size_t)row * ncols + col) = v;
                }
            }
        }
    }
}

// ---------------- reduce: final[n] = sum_e scale[n][e] * part[e][pos[n][e]] ----------------
__global__ void reduce_kernel(float* __restrict__ out, int N, int C, int E) {
    int i = blockIdx.x * blockDim.x + threadIdx.x;
    int per_row = C / 4;
    if (i >= N * per_row) return;
    int n = i / per_row, c4 = i % per_row;
    float4 acc = make_float4(0.f, 0.f, 0.f, 0.f);
    const float* sr = g_scale + (size_t)n * E;
    const int* pr = g_pos + (size_t)n * E;
    for (int e = 0; e < E; e++) {
        float s = sr[e];
        if (s != 0.f) {
            int p = pr[e];
            float4 v = ((const float4*)(g_part + (size_t)e * MAX_N * MAX_C + (size_t)p * C))[c4];
            acc.x += s * v.x; acc.y += s * v.y; acc.z += s * v.z; acc.w += s * v.w;
        }
    }
    ((float4*)(out + (size_t)n * C))[c4] = acc;
}

// ---------------- launch ----------------
extern "C" void kernel_launch(void* const* d_in, const int* in_sizes, int n_in,
                              void* d_out, int out_size) {
    const float* h     = (const float*)d_in[0];
    const float* sim   = (const float*)d_in[1];
    const float* gates = (const float*)d_in[2];
    const float* temp  = (const float*)d_in[3];
    const float* mask  = (const float*)d_in[4];
    const float* w1    = (const float*)d_in[5];
    const float* w2    = (const float*)d_in[6];
    const int*   mi    = (const int*)d_in[7];

    const int E = in_sizes[2];
    const int C = in_sizes[1] / E;
    const int I = in_sizes[5] / (E * C);
    const int N = in_sizes[0] / C;

    float* out_final  = (float*)d_out;
    float* out_logits = out_final + (size_t)N * C;
    float* out_act    = out_logits + (size_t)N * E;

    cudaFuncSetAttribute(mma_gemm<0>, cudaFuncAttributeMaxDynamicSharedMemorySize, SMEM_GEMM);
    cudaFuncSetAttribute(mma_gemm<1>, cudaFuncAttributeMaxDynamicSharedMemorySize, SMEM_GEMM);

    prec_kernel<<<1, 256>>>(sim, temp, C, E);
    gating_kernel<<<N, 128>>>(h, sim, gates, mask, mi, out_logits, out_act, C, E);

    int nb_h  = (N * C) / 1024;            // split_h blocks (256 thr x 4 elems)
    int nb_w1 = E * (C / 32) * (I / 32);
    int nb_w2 = E * (I / 32) * (C / 32);
    prep_kernel<<<nb_h + nb_w1 + nb_w2, 256>>>(h, w1, w2, N, C, I, nb_h, nb_w1);

    mma_gemm<0><<<dim3(I / 128, N / 128, E), 128, SMEM_GEMM>>>(C, I);
    mma_gemm<1><<<dim3(C / 128, N / 128, E), 128, SMEM_GEMM>>>(I, C);

    int rthreads = N * (C / 4);
    reduce_kernel<<<(rthreads + 255) / 256, 256>>>(out_final, N, C, E);
}

// round 11
// speedup vs baseline: 1.1890x; 1.0387x over previous
#include <cuda_runtime.h>
#include <cuda_fp16.h>
#include <math.h>
#include <stdint.h>

// Fixed shapes: N=4096 tokens, C=1024, I=2048, E=8.
#define MAX_N 4096
#define MAX_C 1024
#define MAX_I 2048
#define MAX_E 8

// ---------------- device scratch ----------------
__device__ __align__(256) __half g_h_h[(size_t)MAX_N * MAX_C];                 // fp16 H
__device__ __align__(256) __half g_inter_h[(size_t)MAX_E * MAX_N * MAX_I];     // fp16 inter (compact)
__device__ __align__(256) __half g_w1t[(size_t)MAX_E * MAX_I * MAX_C];         // [E][I][C]
__device__ __align__(256) __half g_w2t[(size_t)MAX_E * MAX_C * MAX_I];         // [E][C][I]
__device__ __align__(256) float g_part[(size_t)MAX_E * MAX_N * MAX_C];         // compact rows
__device__ __align__(256) float g_scale[(size_t)MAX_N * MAX_E];
__device__ __align__(256) int   g_tok[(size_t)MAX_E * MAX_N];
__device__ __align__(256) int   g_pos[(size_t)MAX_N * MAX_E];
__device__ int   g_cnt[MAX_E];
__device__ float g_prec[MAX_E + 1];

#define L2_EPS 1e-12f

// ---------------- PTX helpers (baseline sm_80+ features only) ----------------
__device__ __forceinline__ uint32_t smem_to_u32(const void* p) {
    uint32_t a;
    asm("{ .reg .u64 t; cvta.to.shared.u64 t, %1; cvt.u32.u64 %0, t; }" : "=r"(a) : "l"(p));
    return a;
}
#define CP_ASYNC16(s, g) \
    asm volatile("cp.async.cg.shared.global [%0], [%1], 16;" :: "r"(s), "l"(g))
#define CP_COMMIT() asm volatile("cp.async.commit_group;" ::: "memory")
#define CP_WAIT0()  asm volatile("cp.async.wait_group 0;" ::: "memory")
#define CP_WAIT1()  asm volatile("cp.async.wait_group 1;" ::: "memory")
#define LDSM4(R, addr) \
    asm volatile("ldmatrix.sync.aligned.m8n8.x4.shared.b16 {%0,%1,%2,%3}, [%4];" \
        : "=r"((R)[0]), "=r"((R)[1]), "=r"((R)[2]), "=r"((R)[3]) : "r"(addr))
#define LDSM2(R, addr) \
    asm volatile("ldmatrix.sync.aligned.m8n8.x2.shared.b16 {%0,%1}, [%2];" \
        : "=r"((R)[0]), "=r"((R)[1]) : "r"(addr))
#define MMA16816F16(Cc, A, B) \
    asm volatile("mma.sync.aligned.m16n8k16.row.col.f32.f16.f16.f32 " \
        "{%0,%1,%2,%3}, {%4,%5,%6,%7}, {%8,%9}, {%0,%1,%2,%3};" \
        : "+f"((Cc)[0]), "+f"((Cc)[1]), "+f"((Cc)[2]), "+f"((Cc)[3]) \
        : "r"((A)[0]), "r"((A)[1]), "r"((A)[2]), "r"((A)[3]), "r"((B)[0]), "r"((B)[1]))

// ---------------- prep: sim col norms + logit scale + zero counters ----------------
__global__ void prec_kernel(const float* __restrict__ sim, const float* __restrict__ temp,
                            int C, int E) {
    int w = threadIdx.x >> 5, lane = threadIdx.x & 31;
    if (w < E) {
        float s = 0.f;
        for (int c = lane; c < C; c += 32) { float v = sim[(size_t)c * E + w]; s += v * v; }
        #pragma unroll
        for (int o = 16; o > 0; o >>= 1) s += __shfl_xor_sync(0xffffffffu, s, o);
        if (lane == 0) g_prec[w] = 1.f / fmaxf(sqrtf(s), L2_EPS);
    }
    if (threadIdx.x == 0) g_prec[MAX_E] = 1.f / (1.f + expf(-temp[0]));
    if (threadIdx.x < MAX_E) g_cnt[threadIdx.x] = 0;
}

// ---------------- gating (exact fp32) + fused compaction ----------------
__global__ void gating_kernel(const float* __restrict__ h, const float* __restrict__ sim,
                              const float* __restrict__ gates, const float* __restrict__ mask,
                              const int* __restrict__ min_experts_p,
                              float* __restrict__ out_logits, float* __restrict__ out_act,
                              int C, int E) {
    const int n = blockIdx.x, tid = threadIdx.x;
    float hh = 0.f;
    float dot[MAX_E];
    #pragma unroll
    for (int e = 0; e < MAX_E; e++) dot[e] = 0.f;
    const float* hrow = h + (size_t)n * C;
    for (int c = tid; c < C; c += 128) {
        float v = hrow[c];
        hh += v * v;
        const float* srow = sim + (size_t)c * E;
        #pragma unroll
        for (int e = 0; e < MAX_E; e++) if (e < E) dot[e] += v * srow[e];
    }
    __shared__ float sd[(MAX_E + 1) * 128];
    sd[tid] = hh;
    #pragma unroll
    for (int e = 0; e < MAX_E; e++) if (e < E) sd[(e + 1) * 128 + tid] = dot[e];
    __syncthreads();
    for (int s = 64; s > 0; s >>= 1) {
        if (tid < s)
            for (int r = 0; r <= E; r++) sd[r * 128 + tid] += sd[r * 128 + tid + s];
        __syncthreads();
    }
    if (tid == 0) {
        float inv_h = 1.f / fmaxf(sqrtf(sd[0]), L2_EPS);
        float ls = g_prec[MAX_E];
        float logits[MAX_E], act[MAX_E];
        float suma = 0.f;
        for (int e = 0; e < E; e++) {
            float lg = sd[(e + 1) * 128] * inv_h * g_prec[e];
            lg *= mask[e];
            logits[e] = lg;
            float gated = lg - gates[e] * ls;
            float a = (gated > 0.f) ? 1.f : 0.f;
            act[e] = a; suma += a;
        }
        if (suma == 0.f) {
            int k = min_experts_p ? *min_experts_p : 2;
            if (k <= 0 || k > E) {
                float f = __int_as_float(k);
                int k2 = (int)f;
                k = (k2 > 0 && k2 <= E) ? k2 : 2;
            }
            bool chosen[MAX_E];
            for (int e = 0; e < E; e++) chosen[e] = false;
            for (int j = 0; j < k; j++) {
                int best = -1; float bv = -1e30f;
                for (int e = 0; e < E; e++)
                    if (!chosen[e] && logits[e] > bv) { bv = logits[e]; best = e; }
                if (best >= 0) { chosen[best] = true; act[best] = 1.f; suma += 1.f; }
            }
        }
        float num = fmaxf(suma, 1.f);
        for (int e = 0; e < E; e++) {
            out_logits[(size_t)n * E + e] = logits[e];
            out_act[(size_t)n * E + e] = act[e];
            float sc = act[e] / num;
            g_scale[(size_t)n * E + e] = sc;
            if (sc != 0.f) {                       // fused compaction
                int slot = atomicAdd(&g_cnt[e], 1);
                g_tok[(size_t)e * MAX_N + slot] = n;
                g_pos[(size_t)n * E + e] = slot;
            }
        }
    }
}

// ---------------- fused prep: H -> fp16; W1, W2 -> transposed fp16 ----------------
__global__ void prep_kernel(const float* __restrict__ h,
                            const float* __restrict__ w1, const float* __restrict__ w2,
                            int N, int C, int I, int nb_h, int nb_w1) {
    __shared__ float t[32][33];
    const int bid = blockIdx.x;
    const int tid = threadIdx.x;

    if (bid < nb_h) {
        int i4 = bid * 256 + tid;
        float4 v = ((const float4*)h)[i4];
        __half h0 = __float2half_rn(v.x), h1 = __float2half_rn(v.y);
        __half h2 = __float2half_rn(v.z), h3 = __float2half_rn(v.w);
        uint2 hp;
        hp.x = (uint32_t)__half_as_ushort(h0) | ((uint32_t)__half_as_ushort(h1) << 16);
        hp.y = (uint32_t)__half_as_ushort(h2) | ((uint32_t)__half_as_ushort(h3) << 16);
        ((uint2*)g_h_h)[i4] = hp;
        return;
    }

    const float* src;
    __half* oh;
    int R, Cc, bx, by, e;
    if (bid < nb_h + nb_w1) {
        int b = bid - nb_h;
        R = C; Cc = I;                       // w1: [C][I] per expert
        int per_e = (Cc / 32) * (R / 32);
        e = b / per_e;
        int rem = b % per_e;
        bx = rem % (Cc / 32); by = rem / (Cc / 32);
        src = w1 + (size_t)e * R * Cc;
        oh = g_w1t + (size_t)e * R * Cc;
    } else {
        int b = bid - nb_h - nb_w1;
        R = I; Cc = C;                       // w2: [I][C] per expert
        int per_e = (Cc / 32) * (R / 32);
        e = b / per_e;
        int rem = b % per_e;
        bx = rem % (Cc / 32); by = rem / (Cc / 32);
        src = w2 + (size_t)e * R * Cc;
        oh = g_w2t + (size_t)e * R * Cc;
    }
    const int tx = tid & 31, ty = tid >> 5;  // (32, 8)
    int cbase = bx * 32, rbase = by * 32;
    #pragma unroll
    for (int i = 0; i < 4; i++) {
        int r = rbase + ty + i * 8;
        t[ty + i * 8][tx] = src[(size_t)r * Cc + cbase + tx];
    }
    __syncthreads();
    #pragma unroll
    for (int i = 0; i < 4; i++) {
        int n = cbase + ty + i * 8;
        int k = rbase + tx;
        oh[(size_t)n * R + k] = __float2half_rn(t[tx][ty + i * 8]);
    }
}

// ---------------- HMMA fp16 GEMM, CTA 128x128, 4 warps 64x64, BK=64 ----------------
// Stage: A 128x64 fp16 (pitch 144 B) + B 128x64 fp16 (pitch 144 B) = 36864 B; 2 stages.
// 128 threads/CTA, ~168 regs -> 3 CTAs/SM; 3 x 72 KB = 216 KB SMEM (fits 228 KB).
// MODE 0: inter[e][slot] = gelu(H[tok[e][slot]] @ W1t[e]^T)  K=C, ncols=I (A gathered)
// MODE 1: part[e][slot]  = inter[e][slot] @ W2t[e]^T         K=I, ncols=C (A compact)
static constexpr int PITCH = 144;                        // 128 B row + 16 B pad
static constexpr int TILE_BYTES = 128 * PITCH;           // 18432
static constexpr int STAGE_BYTES = 2 * TILE_BYTES;       // 36864
static constexpr int SMEM_GEMM = 2 * STAGE_BYTES;        // 73728

template <int MODE>
__global__ __launch_bounds__(128)
void mma_gemm(int K, int ncols) {
    extern __shared__ __align__(128) char smem[];
    const int tid = threadIdx.x;
    const int wid = tid >> 5, lane = tid & 31;
    const int e = blockIdx.z;
    const int m0 = blockIdx.y * 128, n0 = blockIdx.x * 128;
    const int wm = wid & 1, wn = (wid >> 1) & 1;   // 2x2 warp grid, 64x64 each

    const int cnt = g_cnt[e];
    if (m0 >= cnt) return;

    const __half* A = (MODE == 0) ? g_h_h : g_inter_h + (size_t)e * MAX_N * MAX_I;
    const __half* B = ((MODE == 0) ? g_w1t : g_w2t) + (size_t)e * ncols * K + (size_t)n0 * K;

    // Copy plan: 128 rows x 8 chunks(16B) per tile; 128 threads -> 8 (row,chunk) tasks each
    // task i: row = (tid>>3) + 16*i, chunk = tid&7
    const int r8 = tid >> 3;
    const int c16 = tid & 7;
    int ga[8];
    #pragma unroll
    for (int i = 0; i < 8; i++) {
        int row = r8 + 16 * i;
        if (MODE == 0) {
            const int* tk = g_tok + (size_t)e * MAX_N;
            ga[i] = tk[min(m0 + row, cnt - 1)];
        } else {
            ga[i] = min(m0 + row, cnt - 1);
        }
    }

    const uint32_t sb = smem_to_u32(smem);

    auto load_stage = [&](int buf, int k0) {
        uint32_t base = sb + (uint32_t)buf * (uint32_t)STAGE_BYTES;
        #pragma unroll
        for (int i = 0; i < 8; i++) {
            int row = r8 + 16 * i;
            uint32_t soff = (uint32_t)row * (uint32_t)PITCH + (uint32_t)c16 * 16u;
            CP_ASYNC16(base + soff,                         A + (size_t)ga[i] * K + k0 + c16 * 8);
            CP_ASYNC16(base + (uint32_t)TILE_BYTES + soff,  B + (size_t)row * K + k0 + c16 * 8);
        }
        CP_COMMIT();
    };

    const int NC = K >> 6;   // K=1024 -> 16, K=2048 -> 32
    load_stage(0, 0);
    load_stage(1, 64);

    float acc[4][8][4];
    #pragma unroll
    for (int a = 0; a < 4; a++)
        #pragma unroll
        for (int b = 0; b < 8; b++)
            #pragma unroll
            for (int d = 0; d < 4; d++) acc[a][b][d] = 0.f;

    for (int c = 0; c < NC; c++) {
        if (c == NC - 1) { CP_WAIT0(); } else { CP_WAIT1(); }
        __syncthreads();
        uint32_t base = sb + (uint32_t)(c & 1) * (uint32_t)STAGE_BYTES;

        #pragma unroll
        for (int ks = 0; ks < 4; ks++) {
            uint32_t Af[4][4], Bf[8][2];
            int arow = wm * 64 + (lane & 15);
            int acolb = (ks * 16 + (lane >> 4) * 8) * 2;
            #pragma unroll
            for (int mt = 0; mt < 4; mt++) {
                uint32_t ad = base + (uint32_t)(arow + mt * 16) * (uint32_t)PITCH + (uint32_t)acolb;
                LDSM4(Af[mt], ad);
            }
            int brow = wn * 64 + (lane & 7);
            int bkb = (ks * 16 + ((lane >> 3) & 1) * 8) * 2;
            #pragma unroll
            for (int nt = 0; nt < 8; nt++) {
                uint32_t bd = base + (uint32_t)TILE_BYTES +
                              (uint32_t)(brow + nt * 8) * (uint32_t)PITCH + (uint32_t)bkb;
                LDSM2(Bf[nt], bd);
            }
            #pragma unroll
            for (int mt = 0; mt < 4; mt++)
                #pragma unroll
                for (int nt = 0; nt < 8; nt++)
                    MMA16816F16(acc[mt][nt], Af[mt], Bf[nt]);
        }
        __syncthreads();
        if (c + 2 < NC) load_stage(c & 1, (c + 2) * 64);
    }

    // ---------------- epilogue (compact rows, guarded by cnt) ----------------
    const int gq = lane >> 2, t2 = (lane & 3) * 2;
    if (MODE == 0) {
        __half* oh = g_inter_h + (size_t)e * MAX_N * MAX_I;
        #pragma unroll
        for (int mt = 0; mt < 4; mt++) {
            #pragma unroll
            for (int nt = 0; nt < 8; nt++) {
                int col = n0 + wn * 64 + nt * 8 + t2;
                #pragma unroll
                for (int hf = 0; hf < 2; hf++) {
                    int row = m0 + wm * 64 + mt * 16 + gq + hf * 8;
                    if (row >= cnt) continue;
                    float x0 = acc[mt][nt][2 * hf];
                    float x1 = acc[mt][nt][2 * hf + 1];
                    float g0 = 0.5f * x0 * (1.f + erff(x0 * 0.70710678118654752f));
                    float g1 = 0.5f * x1 * (1.f + erff(x1 * 0.70710678118654752f));
                    __half h0 = __float2half_rn(g0);
                    __half h1 = __float2half_rn(g1);
                    uint32_t hp = (uint32_t)__half_as_ushort(h0) |
                                  ((uint32_t)__half_as_ushort(h1) << 16);
                    *(uint32_t*)(oh + (size_t)row * ncols + col) = hp;
                }
            }
        }
    } else {
        float* op = g_part + (size_t)e * MAX_N * MAX_C;
        #pragma unroll
        for (int mt = 0; mt < 4; mt++) {
            #pragma unroll
            for (int nt = 0; nt < 8; nt++) {
                int col = n0 + wn * 64 + nt * 8 + t2;
                #pragma unroll
                for (int hf = 0; hf < 2; hf++) {
                    int row = m0 + wm * 64 + mt * 16 + gq + hf * 8;
                    if (row >= cnt) continue;
                    float2 v = make_float2(acc[mt][nt][2 * hf], acc[mt][nt][2 * hf + 1]);
                    *(float2*)(op + (size_t)row * ncols + col) = v;
                }
            }
        }
    }
}

// ---------------- reduce: final[n] = sum_e scale[n][e] * part[e][pos[n][e]] ----------------
__global__ void reduce_kernel(float* __restrict__ out, int N, int C, int E) {
    int i = blockIdx.x * blockDim.x + threadIdx.x;
    int per_row = C / 4;
    if (i >= N * per_row) return;
    int n = i / per_row, c4 = i % per_row;
    float4 acc = make_float4(0.f, 0.f, 0.f, 0.f);
    const float* sr = g_scale + (size_t)n * E;
    const int* pr = g_pos + (size_t)n * E;
    for (int e = 0; e < E; e++) {
        float s = sr[e];
        if (s != 0.f) {
            int p = pr[e];
            float4 v = ((const float4*)(g_part + (size_t)e * MAX_N * MAX_C + (size_t)p * C))[c4];
            acc.x += s * v.x; acc.y += s * v.y; acc.z += s * v.z; acc.w += s * v.w;
        }
    }
    ((float4*)(out + (size_t)n * C))[c4] = acc;
}

// ---------------- launch ----------------
extern "C" void kernel_launch(void* const* d_in, const int* in_sizes, int n_in,
                              void* d_out, int out_size) {
    const float* h     = (const float*)d_in[0];
    const float* sim   = (const float*)d_in[1];
    const float* gates = (const float*)d_in[2];
    const float* temp  = (const float*)d_in[3];
    const float* mask  = (const float*)d_in[4];
    const float* w1    = (const float*)d_in[5];
    const float* w2    = (const float*)d_in[6];
    const int*   mi    = (const int*)d_in[7];

    const int E = in_sizes[2];
    const int C = in_sizes[1] / E;
    const int I = in_sizes[5] / (E * C);
    const int N = in_sizes[0] / C;

    float* out_final  = (float*)d_out;
    float* out_logits = out_final + (size_t)N * C;
    float* out_act    = out_logits + (size_t)N * E;

    cudaFuncSetAttribute(mma_gemm<0>, cudaFuncAttributeMaxDynamicSharedMemorySize, SMEM_GEMM);
    cudaFuncSetAttribute(mma_gemm<1>, cudaFuncAttributeMaxDynamicSharedMemorySize, SMEM_GEMM);

    prec_kernel<<<1, 256>>>(sim, temp, C, E);
    gating_kernel<<<N, 128>>>(h, sim, gates, mask, mi, out_logits, out_act, C, E);

    int nb_h  = (N * C) / 1024;            // split_h blocks (256 thr x 4 elems)
    int nb_w1 = E * (C / 32) * (I / 32);
    int nb_w2 = E * (I / 32) * (C / 32);
    prep_kernel<<<nb_h + nb_w1 + nb_w2, 256>>>(h, w1, w2, N, C, I, nb_h, nb_w1);

    mma_gemm<0><<<dim3(I / 128, N / 128, E), 128, SMEM_GEMM>>>(C, I);
    mma_gemm<1><<<dim3(C / 128, N / 128, E), 128, SMEM_GEMM>>>(I, C);

    int rthreads = N * (C / 4);
    reduce_kernel<<<(rthreads + 255) / 256, 256>>>(out_final, N, C, E);
}

// round 12
// speedup vs baseline: 1.2410x; 1.0437x over previous
#include <cuda_runtime.h>
#include <cuda_fp16.h>
#include <math.h>
#include <stdint.h>

// Fixed shapes: N=4096 tokens, C=1024, I=2048, E=8.
#define MAX_N 4096
#define MAX_C 1024
#define MAX_I 2048
#define MAX_E 8

// ---------------- device scratch ----------------
__device__ __align__(256) __half g_h_h[(size_t)MAX_N * MAX_C];                 // fp16 H
__device__ __align__(256) __half g_inter_h[(size_t)MAX_E * MAX_N * MAX_I];     // fp16 inter (compact)
__device__ __align__(256) __half g_w1t[(size_t)MAX_E * MAX_I * MAX_C];         // [E][I][C]
__device__ __align__(256) __half g_w2t[(size_t)MAX_E * MAX_C * MAX_I];         // [E][C][I]
__device__ __align__(256) float g_part[(size_t)MAX_E * MAX_N * MAX_C];         // compact rows
__device__ __align__(256) float g_scale[(size_t)MAX_N * MAX_E];
__device__ __align__(256) int   g_tok[(size_t)MAX_E * MAX_N];
__device__ __align__(256) int   g_pos[(size_t)MAX_N * MAX_E];
__device__ int   g_cnt[MAX_E];
__device__ float g_prec[MAX_E + 1];

#define L2_EPS 1e-12f

// ---------------- PTX helpers (baseline sm_80+ features only) ----------------
__device__ __forceinline__ uint32_t smem_to_u32(const void* p) {
    uint32_t a;
    asm("{ .reg .u64 t; cvta.to.shared.u64 t, %1; cvt.u32.u64 %0, t; }" : "=r"(a) : "l"(p));
    return a;
}
#define CP_ASYNC16(s, g) \
    asm volatile("cp.async.cg.shared.global [%0], [%1], 16;" :: "r"(s), "l"(g))
#define CP_COMMIT() asm volatile("cp.async.commit_group;" ::: "memory")
#define CP_WAIT0()  asm volatile("cp.async.wait_group 0;" ::: "memory")
#define CP_WAIT1()  asm volatile("cp.async.wait_group 1;" ::: "memory")
#define LDSM4(R, addr) \
    asm volatile("ldmatrix.sync.aligned.m8n8.x4.shared.b16 {%0,%1,%2,%3}, [%4];" \
        : "=r"((R)[0]), "=r"((R)[1]), "=r"((R)[2]), "=r"((R)[3]) : "r"(addr))
#define LDSM2(R, addr) \
    asm volatile("ldmatrix.sync.aligned.m8n8.x2.shared.b16 {%0,%1}, [%2];" \
        : "=r"((R)[0]), "=r"((R)[1]) : "r"(addr))
#define MMA16816F16(Cc, A, B) \
    asm volatile("mma.sync.aligned.m16n8k16.row.col.f32.f16.f16.f32 " \
        "{%0,%1,%2,%3}, {%4,%5,%6,%7}, {%8,%9}, {%0,%1,%2,%3};" \
        : "+f"((Cc)[0]), "+f"((Cc)[1]), "+f"((Cc)[2]), "+f"((Cc)[3]) \
        : "r"((A)[0]), "r"((A)[1]), "r"((A)[2]), "r"((A)[3]), "r"((B)[0]), "r"((B)[1]))

// ---------------- prep: sim col norms + logit scale + zero counters ----------------
__global__ void prec_kernel(const float* __restrict__ sim, const float* __restrict__ temp,
                            int C, int E) {
    int w = threadIdx.x >> 5, lane = threadIdx.x & 31;
    if (w < E) {
        float s = 0.f;
        for (int c = lane; c < C; c += 32) { float v = sim[(size_t)c * E + w]; s += v * v; }
        #pragma unroll
        for (int o = 16; o > 0; o >>= 1) s += __shfl_xor_sync(0xffffffffu, s, o);
        if (lane == 0) g_prec[w] = 1.f / fmaxf(sqrtf(s), L2_EPS);
    }
    if (threadIdx.x == 0) g_prec[MAX_E] = 1.f / (1.f + expf(-temp[0]));
    if (threadIdx.x < MAX_E) g_cnt[threadIdx.x] = 0;
}

// ---------------- gating (exact fp32) + fused compaction ----------------
__global__ void gating_kernel(const float* __restrict__ h, const float* __restrict__ sim,
                              const float* __restrict__ gates, const float* __restrict__ mask,
                              const int* __restrict__ min_experts_p,
                              float* __restrict__ out_logits, float* __restrict__ out_act,
                              int C, int E) {
    const int n = blockIdx.x, tid = threadIdx.x;
    float hh = 0.f;
    float dot[MAX_E];
    #pragma unroll
    for (int e = 0; e < MAX_E; e++) dot[e] = 0.f;
    const float* hrow = h + (size_t)n * C;
    for (int c = tid; c < C; c += 128) {
        float v = hrow[c];
        hh += v * v;
        const float* srow = sim + (size_t)c * E;
        #pragma unroll
        for (int e = 0; e < MAX_E; e++) if (e < E) dot[e] += v * srow[e];
    }
    __shared__ float sd[(MAX_E + 1) * 128];
    sd[tid] = hh;
    #pragma unroll
    for (int e = 0; e < MAX_E; e++) if (e < E) sd[(e + 1) * 128 + tid] = dot[e];
    __syncthreads();
    for (int s = 64; s > 0; s >>= 1) {
        if (tid < s)
            for (int r = 0; r <= E; r++) sd[r * 128 + tid] += sd[r * 128 + tid + s];
        __syncthreads();
    }
    if (tid == 0) {
        float inv_h = 1.f / fmaxf(sqrtf(sd[0]), L2_EPS);
        float ls = g_prec[MAX_E];
        float logits[MAX_E], act[MAX_E];
        float suma = 0.f;
        for (int e = 0; e < E; e++) {
            float lg = sd[(e + 1) * 128] * inv_h * g_prec[e];
            lg *= mask[e];
            logits[e] = lg;
            float gated = lg - gates[e] * ls;
            float a = (gated > 0.f) ? 1.f : 0.f;
            act[e] = a; suma += a;
        }
        if (suma == 0.f) {
            int k = min_experts_p ? *min_experts_p : 2;
            if (k <= 0 || k > E) {
                float f = __int_as_float(k);
                int k2 = (int)f;
                k = (k2 > 0 && k2 <= E) ? k2 : 2;
            }
            bool chosen[MAX_E];
            for (int e = 0; e < E; e++) chosen[e] = false;
            for (int j = 0; j < k; j++) {
                int best = -1; float bv = -1e30f;
                for (int e = 0; e < E; e++)
                    if (!chosen[e] && logits[e] > bv) { bv = logits[e]; best = e; }
                if (best >= 0) { chosen[best] = true; act[best] = 1.f; suma += 1.f; }
            }
        }
        float num = fmaxf(suma, 1.f);
        for (int e = 0; e < E; e++) {
            out_logits[(size_t)n * E + e] = logits[e];
            out_act[(size_t)n * E + e] = act[e];
            float sc = act[e] / num;
            g_scale[(size_t)n * E + e] = sc;
            if (sc != 0.f) {                       // fused compaction
                int slot = atomicAdd(&g_cnt[e], 1);
                g_tok[(size_t)e * MAX_N + slot] = n;
                g_pos[(size_t)n * E + e] = slot;
            }
        }
    }
}

// ---------------- fused prep: H -> fp16; W1, W2 -> transposed fp16 ----------------
__global__ void prep_kernel(const float* __restrict__ h,
                            const float* __restrict__ w1, const float* __restrict__ w2,
                            int N, int C, int I, int nb_h, int nb_w1) {
    __shared__ float t[32][33];
    const int bid = blockIdx.x;
    const int tid = threadIdx.x;

    if (bid < nb_h) {
        int i4 = bid * 256 + tid;
        float4 v = ((const float4*)h)[i4];
        __half h0 = __float2half_rn(v.x), h1 = __float2half_rn(v.y);
        __half h2 = __float2half_rn(v.z), h3 = __float2half_rn(v.w);
        uint2 hp;
        hp.x = (uint32_t)__half_as_ushort(h0) | ((uint32_t)__half_as_ushort(h1) << 16);
        hp.y = (uint32_t)__half_as_ushort(h2) | ((uint32_t)__half_as_ushort(h3) << 16);
        ((uint2*)g_h_h)[i4] = hp;
        return;
    }

    const float* src;
    __half* oh;
    int R, Cc, bx, by, e;
    if (bid < nb_h + nb_w1) {
        int b = bid - nb_h;
        R = C; Cc = I;                       // w1: [C][I] per expert
        int per_e = (Cc / 32) * (R / 32);
        e = b / per_e;
        int rem = b % per_e;
        bx = rem % (Cc / 32); by = rem / (Cc / 32);
        src = w1 + (size_t)e * R * Cc;
        oh = g_w1t + (size_t)e * R * Cc;
    } else {
        int b = bid - nb_h - nb_w1;
        R = I; Cc = C;                       // w2: [I][C] per expert
        int per_e = (Cc / 32) * (R / 32);
        e = b / per_e;
        int rem = b % per_e;
        bx = rem % (Cc / 32); by = rem / (Cc / 32);
        src = w2 + (size_t)e * R * Cc;
        oh = g_w2t + (size_t)e * R * Cc;
    }
    const int tx = tid & 31, ty = tid >> 5;  // (32, 8)
    int cbase = bx * 32, rbase = by * 32;
    #pragma unroll
    for (int i = 0; i < 4; i++) {
        int r = rbase + ty + i * 8;
        t[ty + i * 8][tx] = src[(size_t)r * Cc + cbase + tx];
    }
    __syncthreads();
    #pragma unroll
    for (int i = 0; i < 4; i++) {
        int n = cbase + ty + i * 8;
        int k = rbase + tx;
        oh[(size_t)n * R + k] = __float2half_rn(t[tx][ty + i * 8]);
    }
}

// ---------------- HMMA fp16 GEMM, CTA 128x128, 4 warps 64x64, BK=64 ----------------
// 3-stage cp.async (single barrier / iter) + double-buffered ldmatrix fragments.
// Stage: A 128x64 fp16 (pitch 144 B) + B 128x64 fp16 (pitch 144 B) = 36864 B; 3 stages.
// 128 threads/CTA, ~230-245 regs -> 2 CTAs/SM; 2 x 108 KB = 216 KB SMEM (fits 228 KB).
// MODE 0: inter[e][slot] = gelu(H[tok[e][slot]] @ W1t[e]^T)  K=C, ncols=I (A gathered)
// MODE 1: part[e][slot]  = inter[e][slot] @ W2t[e]^T         K=I, ncols=C (A compact)
static constexpr int PITCH = 144;                        // 128 B row + 16 B pad
static constexpr int TILE_BYTES = 128 * PITCH;           // 18432
static constexpr int STAGE_BYTES = 2 * TILE_BYTES;       // 36864
static constexpr int SMEM_GEMM = 3 * STAGE_BYTES;        // 110592

template <int MODE>
__global__ __launch_bounds__(128, 2)
void mma_gemm(int K, int ncols) {
    extern __shared__ __align__(128) char smem[];
    const int tid = threadIdx.x;
    const int wid = tid >> 5, lane = tid & 31;
    const int e = blockIdx.z;
    const int m0 = blockIdx.y * 128, n0 = blockIdx.x * 128;
    const int wm = wid & 1, wn = (wid >> 1) & 1;   // 2x2 warp grid, 64x64 each

    const int cnt = g_cnt[e];
    if (m0 >= cnt) return;

    const __half* A = (MODE == 0) ? g_h_h : g_inter_h + (size_t)e * MAX_N * MAX_I;
    const __half* B = ((MODE == 0) ? g_w1t : g_w2t) + (size_t)e * ncols * K + (size_t)n0 * K;

    // Copy plan: 128 rows x 8 chunks(16B) per tile; 128 threads -> 8 (row,chunk) tasks each
    const int r8 = tid >> 3;
    const int c16 = tid & 7;
    int ga[8];
    #pragma unroll
    for (int i = 0; i < 8; i++) {
        int row = r8 + 16 * i;
        if (MODE == 0) {
            const int* tk = g_tok + (size_t)e * MAX_N;
            ga[i] = tk[min(m0 + row, cnt - 1)];
        } else {
            ga[i] = min(m0 + row, cnt - 1);
        }
    }

    const uint32_t sb = smem_to_u32(smem);

    auto load_stage = [&](int buf, int k0) {
        uint32_t base = sb + (uint32_t)buf * (uint32_t)STAGE_BYTES;
        #pragma unroll
        for (int i = 0; i < 8; i++) {
            int row = r8 + 16 * i;
            uint32_t soff = (uint32_t)row * (uint32_t)PITCH + (uint32_t)c16 * 16u;
            CP_ASYNC16(base + soff,                         A + (size_t)ga[i] * K + k0 + c16 * 8);
            CP_ASYNC16(base + (uint32_t)TILE_BYTES + soff,  B + (size_t)row * K + k0 + c16 * 8);
        }
        CP_COMMIT();
    };

    uint32_t Af[2][4][4], Bf[2][8][2];
    auto ldfrags = [&](uint32_t base, int ks, uint32_t Afd[4][4], uint32_t Bfd[8][2]) {
        int arow = wm * 64 + (lane & 15);
        int acolb = (ks * 16 + (lane >> 4) * 8) * 2;
        #pragma unroll
        for (int mt = 0; mt < 4; mt++) {
            uint32_t ad = base + (uint32_t)(arow + mt * 16) * (uint32_t)PITCH + (uint32_t)acolb;
            LDSM4(Afd[mt], ad);
        }
        int brow = wn * 64 + (lane & 7);
        int bkb = (ks * 16 + ((lane >> 3) & 1) * 8) * 2;
        #pragma unroll
        for (int nt = 0; nt < 8; nt++) {
            uint32_t bd = base + (uint32_t)TILE_BYTES +
                          (uint32_t)(brow + nt * 8) * (uint32_t)PITCH + (uint32_t)bkb;
            LDSM2(Bfd[nt], bd);
        }
    };

    const int NC = K >> 6;   // K=1024 -> 16, K=2048 -> 32
    load_stage(0, 0);
    load_stage(1, 64);

    float acc[4][8][4];
    #pragma unroll
    for (int a = 0; a < 4; a++)
        #pragma unroll
        for (int b = 0; b < 8; b++)
            #pragma unroll
            for (int d = 0; d < 4; d++) acc[a][b][d] = 0.f;

    int sbuf = 0;                       // stage index mod 3
    for (int c = 0; c < NC; c++) {
        if (c + 1 < NC) { CP_WAIT1(); } else { CP_WAIT0(); }
        __syncthreads();                // protects buffer reuse (consumed in iter c-1)
        uint32_t base = sb + (uint32_t)sbuf * (uint32_t)STAGE_BYTES;
        // Prefetch stage c+2 into buffer (sbuf+2)%3 (consumed in iter c-1; safe after barrier)
        if (c + 2 < NC) {
            int nb = sbuf + 2; if (nb >= 3) nb -= 3;
            load_stage(nb, (c + 2) * 64);
        }
        // Double-buffered fragment pipeline over 4 ks-slices
        ldfrags(base, 0, Af[0], Bf[0]);
        #pragma unroll
        for (int ks = 0; ks < 4; ks++) {
            const int cur = ks & 1;
            if (ks < 3) ldfrags(base, ks + 1, Af[cur ^ 1], Bf[cur ^ 1]);
            #pragma unroll
            for (int mt = 0; mt < 4; mt++)
                #pragma unroll
                for (int nt = 0; nt < 8; nt++)
                    MMA16816F16(acc[mt][nt], Af[cur][mt], Bf[cur][nt]);
        }
        sbuf++; if (sbuf >= 3) sbuf = 0;
    }

    // ---------------- epilogue (compact rows, guarded by cnt) ----------------
    const int gq = lane >> 2, t2 = (lane & 3) * 2;
    if (MODE == 0) {
        __half* oh = g_inter_h + (size_t)e * MAX_N * MAX_I;
        #pragma unroll
        for (int mt = 0; mt < 4; mt++) {
            #pragma unroll
            for (int nt = 0; nt < 8; nt++) {
                int col = n0 + wn * 64 + nt * 8 + t2;
                #pragma unroll
                for (int hf = 0; hf < 2; hf++) {
                    int row = m0 + wm * 64 + mt * 16 + gq + hf * 8;
                    if (row >= cnt) continue;
                    float x0 = acc[mt][nt][2 * hf];
                    float x1 = acc[mt][nt][2 * hf + 1];
                    float g0 = 0.5f * x0 * (1.f + erff(x0 * 0.70710678118654752f));
                    float g1 = 0.5f * x1 * (1.f + erff(x1 * 0.70710678118654752f));
                    __half h0 = __float2half_rn(g0);
                    __half h1 = __float2half_rn(g1);
                    uint32_t hp = (uint32_t)__half_as_ushort(h0) |
                                  ((uint32_t)__half_as_ushort(h1) << 16);
                    *(uint32_t*)(oh + (size_t)row * ncols + col) = hp;
                }
            }
        }
    } else {
        float* op = g_part + (size_t)e * MAX_N * MAX_C;
        #pragma unroll
        for (int mt = 0; mt < 4; mt++) {
            #pragma unroll
            for (int nt = 0; nt < 8; nt++) {
                int col = n0 + wn * 64 + nt * 8 + t2;
                #pragma unroll
                for (int hf = 0; hf < 2; hf++) {
                    int row = m0 + wm * 64 + mt * 16 + gq + hf * 8;
                    if (row >= cnt) continue;
                    float2 v = make_float2(acc[mt][nt][2 * hf], acc[mt][nt][2 * hf + 1]);
                    *(float2*)(op + (size_t)row * ncols + col) = v;
                }
            }
        }
    }
}

// ---------------- reduce: final[n] = sum_e scale[n][e] * part[e][pos[n][e]] ----------------
__global__ void reduce_kernel(float* __restrict__ out, int N, int C, int E) {
    int i = blockIdx.x * blockDim.x + threadIdx.x;
    int per_row = C / 4;
    if (i >= N * per_row) return;
    int n = i / per_row, c4 = i % per_row;
    float4 acc = make_float4(0.f, 0.f, 0.f, 0.f);
    const float* sr = g_scale + (size_t)n * E;
    const int* pr = g_pos + (size_t)n * E;
    for (int e = 0; e < E; e++) {
        float s = sr[e];
        if (s != 0.f) {
            int p = pr[e];
            float4 v = ((const float4*)(g_part + (size_t)e * MAX_N * MAX_C + (size_t)p * C))[c4];
            acc.x += s * v.x; acc.y += s * v.y; acc.z += s * v.z; acc.w += s * v.w;
        }
    }
    ((float4*)(out + (size_t)n * C))[c4] = acc;
}

// ---------------- launch ----------------
extern "C" void kernel_launch(void* const* d_in, const int* in_sizes, int n_in,
                              void* d_out, int out_size) {
    const float* h     = (const float*)d_in[0];
    const float* sim   = (const float*)d_in[1];
    const float* gates = (const float*)d_in[2];
    const float* temp  = (const float*)d_in[3];
    const float* mask  = (const float*)d_in[4];
    const float* w1    = (const float*)d_in[5];
    const float* w2    = (const float*)d_in[6];
    const int*   mi    = (const int*)d_in[7];

    const int E = in_sizes[2];
    const int C = in_sizes[1] / E;
    const int I = in_sizes[5] / (E * C);
    const int N = in_sizes[0] / C;

    float* out_final  = (float*)d_out;
    float* out_logits = out_final + (size_t)N * C;
    float* out_act    = out_logits + (size_t)N * E;

    cudaFuncSetAttribute(mma_gemm<0>, cudaFuncAttributeMaxDynamicSharedMemorySize, SMEM_GEMM);
    cudaFuncSetAttribute(mma_gemm<1>, cudaFuncAttributeMaxDynamicSharedMemorySize, SMEM_GEMM);

    prec_kernel<<<1, 256>>>(sim, temp, C, E);
    gating_kernel<<<N, 128>>>(h, sim, gates, mask, mi, out_logits, out_act, C, E);

    int nb_h  = (N * C) / 1024;            // split_h blocks (256 thr x 4 elems)
    int nb_w1 = E * (C / 32) * (I / 32);
    int nb_w2 = E * (I / 32) * (C / 32);
    prep_kernel<<<nb_h + nb_w1 + nb_w2, 256>>>(h, w1, w2, N, C, I, nb_h, nb_w1);

    mma_gemm<0><<<dim3(I / 128, N / 128, E), 128, SMEM_GEMM>>>(C, I);
    mma_gemm<1><<<dim3(C / 128, N / 128, E), 128, SMEM_GEMM>>>(I, C);

    int rthreads = N * (C / 4);
    reduce_kernel<<<(rthreads + 255) / 256, 256>>>(out_final, N, C, E);
}

// round 13
// speedup vs baseline: 1.2534x; 1.0100x over previous
#include <cuda_runtime.h>
#include <cuda_fp16.h>
#include <math.h>
#include <stdint.h>

// Fixed shapes: N=4096 tokens, C=1024, I=2048, E=8.
#define MAX_N 4096
#define MAX_C 1024
#define MAX_I 2048
#define MAX_E 8

// ---------------- device scratch ----------------
__device__ __align__(256) __half g_h_h[(size_t)MAX_N * MAX_C];                 // fp16 H
__device__ __align__(256) __half g_inter_h[(size_t)MAX_E * MAX_N * MAX_I];     // fp16 inter (compact)
__device__ __align__(256) __half g_w1t[(size_t)MAX_E * MAX_I * MAX_C];         // [E][I][C]
__device__ __align__(256) __half g_w2t[(size_t)MAX_E * MAX_C * MAX_I];         // [E][C][I]
__device__ __align__(256) float g_scale[(size_t)MAX_N * MAX_E];
__device__ __align__(256) int   g_tok[(size_t)MAX_E * MAX_N];
__device__ __align__(256) int   g_pos[(size_t)MAX_N * MAX_E];
__device__ int   g_cnt[MAX_E];
__device__ float g_prec[MAX_E + 1];

#define L2_EPS 1e-12f

// ---------------- PTX helpers (baseline sm_80+ features only) ----------------
__device__ __forceinline__ uint32_t smem_to_u32(const void* p) {
    uint32_t a;
    asm("{ .reg .u64 t; cvta.to.shared.u64 t, %1; cvt.u32.u64 %0, t; }" : "=r"(a) : "l"(p));
    return a;
}
#define CP_ASYNC16(s, g) \
    asm volatile("cp.async.cg.shared.global [%0], [%1], 16;" :: "r"(s), "l"(g))
#define CP_COMMIT() asm volatile("cp.async.commit_group;" ::: "memory")
#define CP_WAIT0()  asm volatile("cp.async.wait_group 0;" ::: "memory")
#define CP_WAIT1()  asm volatile("cp.async.wait_group 1;" ::: "memory")
#define LDSM4(R, addr) \
    asm volatile("ldmatrix.sync.aligned.m8n8.x4.shared.b16 {%0,%1,%2,%3}, [%4];" \
        : "=r"((R)[0]), "=r"((R)[1]), "=r"((R)[2]), "=r"((R)[3]) : "r"(addr))
#define MMA16816F16(Cc, A, B) \
    asm volatile("mma.sync.aligned.m16n8k16.row.col.f32.f16.f16.f32 " \
        "{%0,%1,%2,%3}, {%4,%5,%6,%7}, {%8,%9}, {%0,%1,%2,%3};" \
        : "+f"((Cc)[0]), "+f"((Cc)[1]), "+f"((Cc)[2]), "+f"((Cc)[3]) \
        : "r"((A)[0]), "r"((A)[1]), "r"((A)[2]), "r"((A)[3]), "r"((B)[0]), "r"((B)[1]))

// ---------------- prep: sim col norms + logit scale + zero counters ----------------
__global__ void prec_kernel(const float* __restrict__ sim, const float* __restrict__ temp,
                            int C, int E) {
    int w = threadIdx.x >> 5, lane = threadIdx.x & 31;
    if (w < E) {
        float s = 0.f;
        for (int c = lane; c < C; c += 32) { float v = sim[(size_t)c * E + w]; s += v * v; }
        #pragma unroll
        for (int o = 16; o > 0; o >>= 1) s += __shfl_xor_sync(0xffffffffu, s, o);
        if (lane == 0) g_prec[w] = 1.f / fmaxf(sqrtf(s), L2_EPS);
    }
    if (threadIdx.x == 0) g_prec[MAX_E] = 1.f / (1.f + expf(-temp[0]));
    if (threadIdx.x < MAX_E) g_cnt[threadIdx.x] = 0;
}

// ---------------- gating (exact fp32) + fused compaction ----------------
__global__ void gating_kernel(const float* __restrict__ h, const float* __restrict__ sim,
                              const float* __restrict__ gates, const float* __restrict__ mask,
                              const int* __restrict__ min_experts_p,
                              float* __restrict__ out_logits, float* __restrict__ out_act,
                              int C, int E) {
    const int n = blockIdx.x, tid = threadIdx.x;
    float hh = 0.f;
    float dot[MAX_E];
    #pragma unroll
    for (int e = 0; e < MAX_E; e++) dot[e] = 0.f;
    const float* hrow = h + (size_t)n * C;
    for (int c = tid; c < C; c += 128) {
        float v = hrow[c];
        hh += v * v;
        const float* srow = sim + (size_t)c * E;
        #pragma unroll
        for (int e = 0; e < MAX_E; e++) if (e < E) dot[e] += v * srow[e];
    }
    __shared__ float sd[(MAX_E + 1) * 128];
    sd[tid] = hh;
    #pragma unroll
    for (int e = 0; e < MAX_E; e++) if (e < E) sd[(e + 1) * 128 + tid] = dot[e];
    __syncthreads();
    for (int s = 64; s > 0; s >>= 1) {
        if (tid < s)
            for (int r = 0; r <= E; r++) sd[r * 128 + tid] += sd[r * 128 + tid + s];
        __syncthreads();
    }
    if (tid == 0) {
        float inv_h = 1.f / fmaxf(sqrtf(sd[0]), L2_EPS);
        float ls = g_prec[MAX_E];
        float logits[MAX_E], act[MAX_E];
        float suma = 0.f;
        for (int e = 0; e < E; e++) {
            float lg = sd[(e + 1) * 128] * inv_h * g_prec[e];
            lg *= mask[e];
            logits[e] = lg;
            float gated = lg - gates[e] * ls;
            float a = (gated > 0.f) ? 1.f : 0.f;
            act[e] = a; suma += a;
        }
        if (suma == 0.f) {
            int k = min_experts_p ? *min_experts_p : 2;
            if (k <= 0 || k > E) {
                float f = __int_as_float(k);
                int k2 = (int)f;
                k = (k2 > 0 && k2 <= E) ? k2 : 2;
            }
            bool chosen[MAX_E];
            for (int e = 0; e < E; e++) chosen[e] = false;
            for (int j = 0; j < k; j++) {
                int best = -1; float bv = -1e30f;
                for (int e = 0; e < E; e++)
                    if (!chosen[e] && logits[e] > bv) { bv = logits[e]; best = e; }
                if (best >= 0) { chosen[best] = true; act[best] = 1.f; suma += 1.f; }
            }
        }
        float num = fmaxf(suma, 1.f);
        for (int e = 0; e < E; e++) {
            out_logits[(size_t)n * E + e] = logits[e];
            out_act[(size_t)n * E + e] = act[e];
            float sc = act[e] / num;
            g_scale[(size_t)n * E + e] = sc;
            if (sc != 0.f) {                       // fused compaction
                int slot = atomicAdd(&g_cnt[e], 1);
                g_tok[(size_t)e * MAX_N + slot] = n;
                g_pos[(size_t)n * E + e] = slot;
            }
        }
    }
}

// ---------------- fused prep: H -> fp16; W1, W2 -> transposed fp16 ----------------
__global__ void prep_kernel(const float* __restrict__ h,
                            const float* __restrict__ w1, const float* __restrict__ w2,
                            int N, int C, int I, int nb_h, int nb_w1) {
    __shared__ float t[32][33];
    const int bid = blockIdx.x;
    const int tid = threadIdx.x;

    if (bid < nb_h) {
        int i4 = bid * 256 + tid;
        float4 v = ((const float4*)h)[i4];
        __half h0 = __float2half_rn(v.x), h1 = __float2half_rn(v.y);
        __half h2 = __float2half_rn(v.z), h3 = __float2half_rn(v.w);
        uint2 hp;
        hp.x = (uint32_t)__half_as_ushort(h0) | ((uint32_t)__half_as_ushort(h1) << 16);
        hp.y = (uint32_t)__half_as_ushort(h2) | ((uint32_t)__half_as_ushort(h3) << 16);
        ((uint2*)g_h_h)[i4] = hp;
        return;
    }

    const float* src;
    __half* oh;
    int R, Cc, bx, by, e;
    if (bid < nb_h + nb_w1) {
        int b = bid - nb_h;
        R = C; Cc = I;                       // w1: [C][I] per expert
        int per_e = (Cc / 32) * (R / 32);
        e = b / per_e;
        int rem = b % per_e;
        bx = rem % (Cc / 32); by = rem / (Cc / 32);
        src = w1 + (size_t)e * R * Cc;
        oh = g_w1t + (size_t)e * R * Cc;
    } else {
        int b = bid - nb_h - nb_w1;
        R = I; Cc = C;                       // w2: [I][C] per expert
        int per_e = (Cc / 32) * (R / 32);
        e = b / per_e;
        int rem = b % per_e;
        bx = rem % (Cc / 32); by = rem / (Cc / 32);
        src = w2 + (size_t)e * R * Cc;
        oh = g_w2t + (size_t)e * R * Cc;
    }
    const int tx = tid & 31, ty = tid >> 5;  // (32, 8)
    int cbase = bx * 32, rbase = by * 32;
    #pragma unroll
    for (int i = 0; i < 4; i++) {
        int r = rbase + ty + i * 8;
        t[ty + i * 8][tx] = src[(size_t)r * Cc + cbase + tx];
    }
    __syncthreads();
    #pragma unroll
    for (int i = 0; i < 4; i++) {
        int n = cbase + ty + i * 8;
        int k = rbase + tx;
        oh[(size_t)n * R + k] = __float2half_rn(t[tx][ty + i * 8]);
    }
}

// ---------------- HMMA fp16 GEMM, CTA 128x128, 4 warps 64x64, BK=64 ----------------
// 3-stage cp.async (single barrier / iter) + double-buffered fragments +
// B fragments packed two-nt-per-LDSM4.
// MODE 0: inter[e][slot] = gelu(H[tok[e][slot]] @ W1t[e]^T)  K=C, ncols=I (A gathered)
// MODE 1: out[token]    += scale * (inter[e][slot] @ W2t[e]^T)  (RED epilogue)
static constexpr int PITCH = 144;                        // 128 B row + 16 B pad
static constexpr int TILE_BYTES = 128 * PITCH;           // 18432
static constexpr int STAGE_BYTES = 2 * TILE_BYTES;       // 36864
static constexpr int SMEM_GEMM = 3 * STAGE_BYTES;        // 110592

template <int MODE>
__global__ __launch_bounds__(128, 2)
void mma_gemm(int K, int ncols, float* __restrict__ out) {
    extern __shared__ __align__(128) char smem[];
    const int tid = threadIdx.x;
    const int wid = tid >> 5, lane = tid & 31;
    const int e = blockIdx.z;
    const int m0 = blockIdx.y * 128, n0 = blockIdx.x * 128;
    const int wm = wid & 1, wn = (wid >> 1) & 1;   // 2x2 warp grid, 64x64 each

    const int cnt = g_cnt[e];
    if (m0 >= cnt) return;

    const __half* A = (MODE == 0) ? g_h_h : g_inter_h + (size_t)e * MAX_N * MAX_I;
    const __half* B = ((MODE == 0) ? g_w1t : g_w2t) + (size_t)e * ncols * K + (size_t)n0 * K;

    // Copy plan: 128 rows x 8 chunks(16B) per tile; 128 threads -> 8 (row,chunk) tasks each
    const int r8 = tid >> 3;
    const int c16 = tid & 7;
    int ga[8];
    #pragma unroll
    for (int i = 0; i < 8; i++) {
        int row = r8 + 16 * i;
        if (MODE == 0) {
            const int* tk = g_tok + (size_t)e * MAX_N;
            ga[i] = tk[min(m0 + row, cnt - 1)];
        } else {
            ga[i] = min(m0 + row, cnt - 1);
        }
    }

    const uint32_t sb = smem_to_u32(smem);

    auto load_stage = [&](int buf, int k0) {
        uint32_t base = sb + (uint32_t)buf * (uint32_t)STAGE_BYTES;
        #pragma unroll
        for (int i = 0; i < 8; i++) {
            int row = r8 + 16 * i;
            uint32_t soff = (uint32_t)row * (uint32_t)PITCH + (uint32_t)c16 * 16u;
            CP_ASYNC16(base + soff,                         A + (size_t)ga[i] * K + k0 + c16 * 8);
            CP_ASYNC16(base + (uint32_t)TILE_BYTES + soff,  B + (size_t)row * K + k0 + c16 * 8);
        }
        CP_COMMIT();
    };

    uint32_t Af[2][4][4], Bf[2][8][2];
    auto ldfrags = [&](uint32_t base, int ks, uint32_t Afd[4][4], uint32_t Bfd[8][2]) {
        int arow = wm * 64 + (lane & 15);
        int acolb = (ks * 16 + (lane >> 4) * 8) * 2;
        #pragma unroll
        for (int mt = 0; mt < 4; mt++) {
            uint32_t ad = base + (uint32_t)(arow + mt * 16) * (uint32_t)PITCH + (uint32_t)acolb;
            LDSM4(Afd[mt], ad);
        }
        // B: two nt blocks per LDSM4.
        // lanes 0-7:  rows nt*16 + 0-7,  k-half 0   (mat0 = Bf[2i][0])
        // lanes 8-15: rows nt*16 + 0-7,  k-half 1   (mat1 = Bf[2i][1])
        // lanes 16-23: rows nt*16 + 8-15, k-half 0  (mat2 = Bf[2i+1][0])
        // lanes 24-31: rows nt*16 + 8-15, k-half 1  (mat3 = Bf[2i+1][1])
        int brow = wn * 64 + (lane & 7) + (((lane >> 4) & 1) << 3);
        int bkb = (ks * 16 + ((lane >> 3) & 1) * 8) * 2;
        #pragma unroll
        for (int nt4 = 0; nt4 < 4; nt4++) {
            uint32_t bd = base + (uint32_t)TILE_BYTES +
                          (uint32_t)(brow + nt4 * 16) * (uint32_t)PITCH + (uint32_t)bkb;
            LDSM4((&Bfd[2 * nt4][0]), bd);
        }
    };

    const int NC = K >> 6;   // K=1024 -> 16, K=2048 -> 32
    load_stage(0, 0);
    load_stage(1, 64);

    float acc[4][8][4];
    #pragma unroll
    for (int a = 0; a < 4; a++)
        #pragma unroll
        for (int b = 0; b < 8; b++)
            #pragma unroll
            for (int d = 0; d < 4; d++) acc[a][b][d] = 0.f;

    int sbuf = 0;                       // stage index mod 3
    for (int c = 0; c < NC; c++) {
        if (c + 1 < NC) { CP_WAIT1(); } else { CP_WAIT0(); }
        __syncthreads();                // protects buffer reuse (consumed in iter c-1)
        uint32_t base = sb + (uint32_t)sbuf * (uint32_t)STAGE_BYTES;
        if (c + 2 < NC) {
            int nb = sbuf + 2; if (nb >= 3) nb -= 3;
            load_stage(nb, (c + 2) * 64);
        }
        ldfrags(base, 0, Af[0], Bf[0]);
        #pragma unroll
        for (int ks = 0; ks < 4; ks++) {
            const int cur = ks & 1;
            if (ks < 3) ldfrags(base, ks + 1, Af[cur ^ 1], Bf[cur ^ 1]);
            #pragma unroll
            for (int mt = 0; mt < 4; mt++)
                #pragma unroll
                for (int nt = 0; nt < 8; nt++)
                    MMA16816F16(acc[mt][nt], Af[cur][mt], Bf[cur][nt]);
        }
        sbuf++; if (sbuf >= 3) sbuf = 0;
    }

    // ---------------- epilogue ----------------
    const int gq = lane >> 2, t2 = (lane & 3) * 2;
    if (MODE == 0) {
        __half* oh = g_inter_h + (size_t)e * MAX_N * MAX_I;
        #pragma unroll
        for (int mt = 0; mt < 4; mt++) {
            #pragma unroll
            for (int nt = 0; nt < 8; nt++) {
                int col = n0 + wn * 64 + nt * 8 + t2;
                #pragma unroll
                for (int hf = 0; hf < 2; hf++) {
                    int row = m0 + wm * 64 + mt * 16 + gq + hf * 8;
                    if (row >= cnt) continue;
                    float x0 = acc[mt][nt][2 * hf];
                    float x1 = acc[mt][nt][2 * hf + 1];
                    float g0 = 0.5f * x0 * (1.f + erff(x0 * 0.70710678118654752f));
                    float g1 = 0.5f * x1 * (1.f + erff(x1 * 0.70710678118654752f));
                    __half h0 = __float2half_rn(g0);
                    __half h1 = __float2half_rn(g1);
                    uint32_t hp = (uint32_t)__half_as_ushort(h0) |
                                  ((uint32_t)__half_as_ushort(h1) << 16);
                    *(uint32_t*)(oh + (size_t)row * ncols + col) = hp;
                }
            }
        }
    } else {
        // Fused scatter-reduce: out[token] += scale * acc  (RED, no return)
        const int* tk = g_tok + (size_t)e * MAX_N;
        #pragma unroll
        for (int mt = 0; mt < 4; mt++) {
            #pragma unroll
            for (int hf = 0; hf < 2; hf++) {
                int row = m0 + wm * 64 + mt * 16 + gq + hf * 8;
                if (row >= cnt) continue;
                int token = tk[row];
                float sc = g_scale[(size_t)token * MAX_E + e];
                float* orow = out + (size_t)token * ncols;
                #pragma unroll
                for (int nt = 0; nt < 8; nt++) {
                    int col = n0 + wn * 64 + nt * 8 + t2;
                    atomicAdd(&orow[col],     sc * acc[mt][nt][2 * hf]);
                    atomicAdd(&orow[col + 1], sc * acc[mt][nt][2 * hf + 1]);
                }
            }
        }
    }
}

// ---------------- launch ----------------
extern "C" void kernel_launch(void* const* d_in, const int* in_sizes, int n_in,
                              void* d_out, int out_size) {
    const float* h     = (const float*)d_in[0];
    const float* sim   = (const float*)d_in[1];
    const float* gates = (const float*)d_in[2];
    const float* temp  = (const float*)d_in[3];
    const float* mask  = (const float*)d_in[4];
    const float* w1    = (const float*)d_in[5];
    const float* w2    = (const float*)d_in[6];
    const int*   mi    = (const int*)d_in[7];

    const int E = in_sizes[2];
    const int C = in_sizes[1] / E;
    const int I = in_sizes[5] / (E * C);
    const int N = in_sizes[0] / C;

    float* out_final  = (float*)d_out;
    float* out_logits = out_final + (size_t)N * C;
    float* out_act    = out_logits + (size_t)N * E;

    cudaFuncSetAttribute(mma_gemm<0>, cudaFuncAttributeMaxDynamicSharedMemorySize, SMEM_GEMM);
    cudaFuncSetAttribute(mma_gemm<1>, cudaFuncAttributeMaxDynamicSharedMemorySize, SMEM_GEMM);

    cudaMemsetAsync(out_final, 0, (size_t)N * C * sizeof(float));
    prec_kernel<<<1, 256>>>(sim, temp, C, E);
    gating_kernel<<<N, 128>>>(h, sim, gates, mask, mi, out_logits, out_act, C, E);

    int nb_h  = (N * C) / 1024;            // split_h blocks (256 thr x 4 elems)
    int nb_w1 = E * (C / 32) * (I / 32);
    int nb_w2 = E * (I / 32) * (C / 32);
    prep_kernel<<<nb_h + nb_w1 + nb_w2, 256>>>(h, w1, w2, N, C, I, nb_h, nb_w1);

    mma_gemm<0><<<dim3(I / 128, N / 128, E), 128, SMEM_GEMM>>>(C, I, nullptr);
    mma_gemm<1><<<dim3(C / 128, N / 128, E), 128, SMEM_GEMM>>>(I, C, out_final);
}

// round 14
// speedup vs baseline: 1.3056x; 1.0416x over previous
#include <cuda_runtime.h>
#include <cuda_fp16.h>
#include <math.h>
#include <stdint.h>

// Fixed shapes: N=4096 tokens, C=1024, I=2048, E=8.
#define MAX_N 4096
#define MAX_C 1024
#define MAX_I 2048
#define MAX_E 8

// ---------------- device scratch ----------------
__device__ __align__(256) __half g_h_h[(size_t)MAX_N * MAX_C];                 // fp16 H
__device__ __align__(256) __half g_inter_h[(size_t)MAX_E * MAX_N * MAX_I];     // fp16 inter (compact)
__device__ __align__(256) __half g_w1t[(size_t)MAX_E * MAX_I * MAX_C];         // [E][I][C]
__device__ __align__(256) __half g_w2t[(size_t)MAX_E * MAX_C * MAX_I];         // [E][C][I]
__device__ __align__(256) float g_scale[(size_t)MAX_N * MAX_E];
__device__ __align__(256) int   g_tok[(size_t)MAX_E * MAX_N];
__device__ __align__(256) int   g_pos[(size_t)MAX_N * MAX_E];
__device__ int   g_cnt[MAX_E];
__device__ float g_prec[MAX_E + 1];

#define L2_EPS 1e-12f

// ---------------- PTX helpers (baseline sm_80+ features only) ----------------
__device__ __forceinline__ uint32_t smem_to_u32(const void* p) {
    uint32_t a;
    asm("{ .reg .u64 t; cvta.to.shared.u64 t, %1; cvt.u32.u64 %0, t; }" : "=r"(a) : "l"(p));
    return a;
}
#define CP_ASYNC16(s, g) \
    asm volatile("cp.async.cg.shared.global [%0], [%1], 16;" :: "r"(s), "l"(g))
#define CP_COMMIT() asm volatile("cp.async.commit_group;" ::: "memory")
#define CP_WAIT0()  asm volatile("cp.async.wait_group 0;" ::: "memory")
#define CP_WAIT1()  asm volatile("cp.async.wait_group 1;" ::: "memory")
#define LDSM4(R, addr) \
    asm volatile("ldmatrix.sync.aligned.m8n8.x4.shared.b16 {%0,%1,%2,%3}, [%4];" \
        : "=r"((R)[0]), "=r"((R)[1]), "=r"((R)[2]), "=r"((R)[3]) : "r"(addr))
#define MMA16816F16(Cc, A, B) \
    asm volatile("mma.sync.aligned.m16n8k16.row.col.f32.f16.f16.f32 " \
        "{%0,%1,%2,%3}, {%4,%5,%6,%7}, {%8,%9}, {%0,%1,%2,%3};" \
        : "+f"((Cc)[0]), "+f"((Cc)[1]), "+f"((Cc)[2]), "+f"((Cc)[3]) \
        : "r"((A)[0]), "r"((A)[1]), "r"((A)[2]), "r"((A)[3]), "r"((B)[0]), "r"((B)[1]))

// ---------------- prep: sim col norms + logit scale + zero counters ----------------
__global__ void prec_kernel(const float* __restrict__ sim, const float* __restrict__ temp,
                            int C, int E) {
    int w = threadIdx.x >> 5, lane = threadIdx.x & 31;
    if (w < E) {
        float s = 0.f;
        for (int c = lane; c < C; c += 32) { float v = sim[(size_t)c * E + w]; s += v * v; }
        #pragma unroll
        for (int o = 16; o > 0; o >>= 1) s += __shfl_xor_sync(0xffffffffu, s, o);
        if (lane == 0) g_prec[w] = 1.f / fmaxf(sqrtf(s), L2_EPS);
    }
    if (threadIdx.x == 0) g_prec[MAX_E] = 1.f / (1.f + expf(-temp[0]));
    if (threadIdx.x < MAX_E) g_cnt[threadIdx.x] = 0;
}

// ---------------- gating (exact fp32) + fused compaction ----------------
__global__ void gating_kernel(const float* __restrict__ h, const float* __restrict__ sim,
                              const float* __restrict__ gates, const float* __restrict__ mask,
                              const int* __restrict__ min_experts_p,
                              float* __restrict__ out_logits, float* __restrict__ out_act,
                              int C, int E) {
    const int n = blockIdx.x, tid = threadIdx.x;
    float hh = 0.f;
    float dot[MAX_E];
    #pragma unroll
    for (int e = 0; e < MAX_E; e++) dot[e] = 0.f;
    const float* hrow = h + (size_t)n * C;
    for (int c = tid; c < C; c += 128) {
        float v = hrow[c];
        hh += v * v;
        const float* srow = sim + (size_t)c * E;
        #pragma unroll
        for (int e = 0; e < MAX_E; e++) if (e < E) dot[e] += v * srow[e];
    }
    __shared__ float sd[(MAX_E + 1) * 128];
    sd[tid] = hh;
    #pragma unroll
    for (int e = 0; e < MAX_E; e++) if (e < E) sd[(e + 1) * 128 + tid] = dot[e];
    __syncthreads();
    for (int s = 64; s > 0; s >>= 1) {
        if (tid < s)
            for (int r = 0; r <= E; r++) sd[r * 128 + tid] += sd[r * 128 + tid + s];
        __syncthreads();
    }
    if (tid == 0) {
        float inv_h = 1.f / fmaxf(sqrtf(sd[0]), L2_EPS);
        float ls = g_prec[MAX_E];
        float logits[MAX_E], act[MAX_E];
        float suma = 0.f;
        for (int e = 0; e < E; e++) {
            float lg = sd[(e + 1) * 128] * inv_h * g_prec[e];
            lg *= mask[e];
            logits[e] = lg;
            float gated = lg - gates[e] * ls;
            float a = (gated > 0.f) ? 1.f : 0.f;
            act[e] = a; suma += a;
        }
        if (suma == 0.f) {
            int k = min_experts_p ? *min_experts_p : 2;
            if (k <= 0 || k > E) {
                float f = __int_as_float(k);
                int k2 = (int)f;
                k = (k2 > 0 && k2 <= E) ? k2 : 2;
            }
            bool chosen[MAX_E];
            for (int e = 0; e < E; e++) chosen[e] = false;
            for (int j = 0; j < k; j++) {
                int best = -1; float bv = -1e30f;
                for (int e = 0; e < E; e++)
                    if (!chosen[e] && logits[e] > bv) { bv = logits[e]; best = e; }
                if (best >= 0) { chosen[best] = true; act[best] = 1.f; suma += 1.f; }
            }
        }
        float num = fmaxf(suma, 1.f);
        for (int e = 0; e < E; e++) {
            out_logits[(size_t)n * E + e] = logits[e];
            out_act[(size_t)n * E + e] = act[e];
            float sc = act[e] / num;
            g_scale[(size_t)n * E + e] = sc;
            if (sc != 0.f) {                       // fused compaction
                int slot = atomicAdd(&g_cnt[e], 1);
                g_tok[(size_t)e * MAX_N + slot] = n;
                g_pos[(size_t)n * E + e] = slot;
            }
        }
    }
}

// ---------------- fused prep: H -> fp16; W1, W2 -> transposed fp16 ----------------
__global__ void prep_kernel(const float* __restrict__ h,
                            const float* __restrict__ w1, const float* __restrict__ w2,
                            int N, int C, int I, int nb_h, int nb_w1) {
    __shared__ float t[32][33];
    const int bid = blockIdx.x;
    const int tid = threadIdx.x;

    if (bid < nb_h) {
        int i4 = bid * 256 + tid;
        float4 v = ((const float4*)h)[i4];
        __half h0 = __float2half_rn(v.x), h1 = __float2half_rn(v.y);
        __half h2 = __float2half_rn(v.z), h3 = __float2half_rn(v.w);
        uint2 hp;
        hp.x = (uint32_t)__half_as_ushort(h0) | ((uint32_t)__half_as_ushort(h1) << 16);
        hp.y = (uint32_t)__half_as_ushort(h2) | ((uint32_t)__half_as_ushort(h3) << 16);
        ((uint2*)g_h_h)[i4] = hp;
        return;
    }

    const float* src;
    __half* oh;
    int R, Cc, bx, by, e;
    if (bid < nb_h + nb_w1) {
        int b = bid - nb_h;
        R = C; Cc = I;                       // w1: [C][I] per expert
        int per_e = (Cc / 32) * (R / 32);
        e = b / per_e;
        int rem = b % per_e;
        bx = rem % (Cc / 32); by = rem / (Cc / 32);
        src = w1 + (size_t)e * R * Cc;
        oh = g_w1t + (size_t)e * R * Cc;
    } else {
        int b = bid - nb_h - nb_w1;
        R = I; Cc = C;                       // w2: [I][C] per expert
        int per_e = (Cc / 32) * (R / 32);
        e = b / per_e;
        int rem = b % per_e;
        bx = rem % (Cc / 32); by = rem / (Cc / 32);
        src = w2 + (size_t)e * R * Cc;
        oh = g_w2t + (size_t)e * R * Cc;
    }
    const int tx = tid & 31, ty = tid >> 5;  // (32, 8)
    int cbase = bx * 32, rbase = by * 32;
    #pragma unroll
    for (int i = 0; i < 4; i++) {
        int r = rbase + ty + i * 8;
        t[ty + i * 8][tx] = src[(size_t)r * Cc + cbase + tx];
    }
    __syncthreads();
    #pragma unroll
    for (int i = 0; i < 4; i++) {
        int n = cbase + ty + i * 8;
        int k = rbase + tx;
        oh[(size_t)n * R + k] = __float2half_rn(t[tx][ty + i * 8]);
    }
}

// ---------------- HMMA fp16 GEMM, CTA 128x128, 4 warps 64x64, BK=64 ----------------
// Register-dieted for 3 CTAs/SM: single Af buffer, B fragments consumed
// immediately (live set 4 regs), gather indices recomputed in load_stage.
// 2-stage double buffer: 2 x 36864 = 73728 B/CTA; 3 CTAs = 216 KB (fits 228 KB).
// MODE 0: inter[e][slot] = gelu(H[tok[e][slot]] @ W1t[e]^T)  K=C, ncols=I (A gathered)
// MODE 1: out[token]    += scale * (inter[e][slot] @ W2t[e]^T)  (RED epilogue)
static constexpr int PITCH = 144;                        // 128 B row + 16 B pad
static constexpr int TILE_BYTES = 128 * PITCH;           // 18432
static constexpr int STAGE_BYTES = 2 * TILE_BYTES;       // 36864
static constexpr int SMEM_GEMM = 2 * STAGE_BYTES;        // 73728

template <int MODE>
__global__ __launch_bounds__(128, 3)
void mma_gemm(int K, int ncols, float* __restrict__ out) {
    extern __shared__ __align__(128) char smem[];
    const int tid = threadIdx.x;
    const int wid = tid >> 5, lane = tid & 31;
    const int e = blockIdx.z;
    const int m0 = blockIdx.y * 128, n0 = blockIdx.x * 128;
    const int wm = wid & 1, wn = (wid >> 1) & 1;   // 2x2 warp grid, 64x64 each

    const int cnt = g_cnt[e];
    if (m0 >= cnt) return;

    const __half* A = (MODE == 0) ? g_h_h : g_inter_h + (size_t)e * MAX_N * MAX_I;
    const __half* B = ((MODE == 0) ? g_w1t : g_w2t) + (size_t)e * ncols * K + (size_t)n0 * K;
    const int* tk = g_tok + (size_t)e * MAX_N;

    // Copy plan: 128 rows x 8 chunks(16B) per tile; 8 (row,chunk) tasks per thread.
    const int r8 = tid >> 3;
    const int c16 = tid & 7;

    const uint32_t sb = smem_to_u32(smem);

    auto load_stage = [&](int buf, int k0) {
        uint32_t base = sb + (uint32_t)buf * (uint32_t)STAGE_BYTES;
        #pragma unroll
        for (int i = 0; i < 8; i++) {
            int row = r8 + 16 * i;
            int arow;
            if (MODE == 0) arow = tk[min(m0 + row, cnt - 1)];
            else           arow = min(m0 + row, cnt - 1);
            uint32_t soff = (uint32_t)row * (uint32_t)PITCH + (uint32_t)c16 * 16u;
            CP_ASYNC16(base + soff,                         A + (size_t)arow * K + k0 + c16 * 8);
            CP_ASYNC16(base + (uint32_t)TILE_BYTES + soff,  B + (size_t)row * K + k0 + c16 * 8);
        }
        CP_COMMIT();
    };

    const int NC = K >> 6;   // K=1024 -> 16, K=2048 -> 32
    load_stage(0, 0);
    load_stage(1, 64);

    float acc[4][8][4];
    #pragma unroll
    for (int a = 0; a < 4; a++)
        #pragma unroll
        for (int b = 0; b < 8; b++)
            #pragma unroll
            for (int d = 0; d < 4; d++) acc[a][b][d] = 0.f;

    for (int c = 0; c < NC; c++) {
        if (c == NC - 1) { CP_WAIT0(); } else { CP_WAIT1(); }
        __syncthreads();
        uint32_t base = sb + (uint32_t)(c & 1) * (uint32_t)STAGE_BYTES;

        #pragma unroll
        for (int ks = 0; ks < 4; ks++) {
            uint32_t Af[4][4];
            int arow = wm * 64 + (lane & 15);
            int acolb = (ks * 16 + (lane >> 4) * 8) * 2;
            #pragma unroll
            for (int mt = 0; mt < 4; mt++) {
                uint32_t ad = base + (uint32_t)(arow + mt * 16) * (uint32_t)PITCH + (uint32_t)acolb;
                LDSM4(Af[mt], ad);
            }
            // B: two nt blocks per packed LDSM4, consumed immediately (live = 4 regs).
            int brow = wn * 64 + (lane & 7) + (((lane >> 4) & 1) << 3);
            int bkb = (ks * 16 + ((lane >> 3) & 1) * 8) * 2;
            #pragma unroll
            for (int nt4 = 0; nt4 < 4; nt4++) {
                uint32_t Bp[4];
                uint32_t bd = base + (uint32_t)TILE_BYTES +
                              (uint32_t)(brow + nt4 * 16) * (uint32_t)PITCH + (uint32_t)bkb;
                LDSM4(Bp, bd);
                #pragma unroll
                for (int mt = 0; mt < 4; mt++) {
                    MMA16816F16(acc[mt][2 * nt4],     Af[mt], (&Bp[0]));
                    MMA16816F16(acc[mt][2 * nt4 + 1], Af[mt], (&Bp[2]));
                }
            }
        }
        __syncthreads();
        if (c + 2 < NC) load_stage(c & 1, (c + 2) * 64);
    }

    // ---------------- epilogue ----------------
    const int gq = lane >> 2, t2 = (lane & 3) * 2;
    if (MODE == 0) {
        __half* oh = g_inter_h + (size_t)e * MAX_N * MAX_I;
        #pragma unroll
        for (int mt = 0; mt < 4; mt++) {
            #pragma unroll
            for (int nt = 0; nt < 8; nt++) {
                int col = n0 + wn * 64 + nt * 8 + t2;
                #pragma unroll
                for (int hf = 0; hf < 2; hf++) {
                    int row = m0 + wm * 64 + mt * 16 + gq + hf * 8;
                    if (row >= cnt) continue;
                    float x0 = acc[mt][nt][2 * hf];
                    float x1 = acc[mt][nt][2 * hf + 1];
                    float g0 = 0.5f * x0 * (1.f + erff(x0 * 0.70710678118654752f));
                    float g1 = 0.5f * x1 * (1.f + erff(x1 * 0.70710678118654752f));
                    __half h0 = __float2half_rn(g0);
                    __half h1 = __float2half_rn(g1);
                    uint32_t hp = (uint32_t)__half_as_ushort(h0) |
                                  ((uint32_t)__half_as_ushort(h1) << 16);
                    *(uint32_t*)(oh + (size_t)row * ncols + col) = hp;
                }
            }
        }
    } else {
        // Fused scatter-reduce: out[token] += scale * acc  (RED, no return)
        #pragma unroll
        for (int mt = 0; mt < 4; mt++) {
            #pragma unroll
            for (int hf = 0; hf < 2; hf++) {
                int row = m0 + wm * 64 + mt * 16 + gq + hf * 8;
                if (row >= cnt) continue;
                int token = tk[row];
                float sc = g_scale[(size_t)token * MAX_E + e];
                float* orow = out + (size_t)token * ncols;
                #pragma unroll
                for (int nt = 0; nt < 8; nt++) {
                    int col = n0 + wn * 64 + nt * 8 + t2;
                    atomicAdd(&orow[col],     sc * acc[mt][nt][2 * hf]);
                    atomicAdd(&orow[col + 1], sc * acc[mt][nt][2 * hf + 1]);
                }
            }
        }
    }
}

// ---------------- launch ----------------
extern "C" void kernel_launch(void* const* d_in, const int* in_sizes, int n_in,
                              void* d_out, int out_size) {
    const float* h     = (const float*)d_in[0];
    const float* sim   = (const float*)d_in[1];
    const float* gates = (const float*)d_in[2];
    const float* temp  = (const float*)d_in[3];
    const float* mask  = (const float*)d_in[4];
    const float* w1    = (const float*)d_in[5];
    const float* w2    = (const float*)d_in[6];
    const int*   mi    = (const int*)d_in[7];

    const int E = in_sizes[2];
    const int C = in_sizes[1] / E;
    const int I = in_sizes[5] / (E * C);
    const int N = in_sizes[0] / C;

    float* out_final  = (float*)d_out;
    float* out_logits = out_final + (size_t)N * C;
    float* out_act    = out_logits + (size_t)N * E;

    cudaFuncSetAttribute(mma_gemm<0>, cudaFuncAttributeMaxDynamicSharedMemorySize, SMEM_GEMM);
    cudaFuncSetAttribute(mma_gemm<1>, cudaFuncAttributeMaxDynamicSharedMemorySize, SMEM_GEMM);

    cudaMemsetAsync(out_final, 0, (size_t)N * C * sizeof(float));
    prec_kernel<<<1, 256>>>(sim, temp, C, E);
    gating_kernel<<<N, 128>>>(h, sim, gates, mask, mi, out_logits, out_act, C, E);

    int nb_h  = (N * C) / 1024;            // split_h blocks (256 thr x 4 elems)
    int nb_w1 = E * (C / 32) * (I / 32);
    int nb_w2 = E * (I / 32) * (C / 32);
    prep_kernel<<<nb_h + nb_w1 + nb_w2, 256>>>(h, w1, w2, N, C, I, nb_h, nb_w1);

    mma_gemm<0><<<dim3(I / 128, N / 128, E), 128, SMEM_GEMM>>>(C, I, nullptr);
    mma_gemm<1><<<dim3(C / 128, N / 128, E), 128, SMEM_GEMM>>>(I, C, out_final);
}

// round 15
// speedup vs baseline: 1.3390x; 1.0256x over previous
#include <cuda_runtime.h>
#include <cuda_fp16.h>
#include <math.h>
#include <stdint.h>

// Fixed shapes: N=4096 tokens, C=1024, I=2048, E=8.
#define MAX_N 4096
#define MAX_C 1024
#define MAX_I 2048
#define MAX_E 8

// ---------------- device scratch ----------------
__device__ __align__(256) __half g_h_h[(size_t)MAX_N * MAX_C];                 // fp16 H
__device__ __align__(256) __half g_inter_h[(size_t)MAX_E * MAX_N * MAX_I];     // fp16 inter (compact)
__device__ __align__(256) __half g_w1t[(size_t)MAX_E * MAX_I * MAX_C];         // [E][I][C]
__device__ __align__(256) __half g_w2t[(size_t)MAX_E * MAX_C * MAX_I];         // [E][C][I]
__device__ __align__(256) float g_scale[(size_t)MAX_N * MAX_E];
__device__ __align__(256) int   g_tok[(size_t)MAX_E * MAX_N];
__device__ __align__(256) int   g_pos[(size_t)MAX_N * MAX_E];
__device__ int   g_cnt[MAX_E];
__device__ float g_prec[MAX_E + 1];

#define L2_EPS 1e-12f

// ---------------- PTX helpers (baseline sm_80+ features only) ----------------
__device__ __forceinline__ uint32_t smem_to_u32(const void* p) {
    uint32_t a;
    asm("{ .reg .u64 t; cvta.to.shared.u64 t, %1; cvt.u32.u64 %0, t; }" : "=r"(a) : "l"(p));
    return a;
}
#define CP_ASYNC16(s, g) \
    asm volatile("cp.async.cg.shared.global [%0], [%1], 16;" :: "r"(s), "l"(g))
#define CP_COMMIT() asm volatile("cp.async.commit_group;" ::: "memory")
#define CP_WAIT0()  asm volatile("cp.async.wait_group 0;" ::: "memory")
#define CP_WAIT1()  asm volatile("cp.async.wait_group 1;" ::: "memory")
#define LDSM4(R, addr) \
    asm volatile("ldmatrix.sync.aligned.m8n8.x4.shared.b16 {%0,%1,%2,%3}, [%4];" \
        : "=r"((R)[0]), "=r"((R)[1]), "=r"((R)[2]), "=r"((R)[3]) : "r"(addr))
#define MMA16816F16(Cc, A, B) \
    asm volatile("mma.sync.aligned.m16n8k16.row.col.f32.f16.f16.f32 " \
        "{%0,%1,%2,%3}, {%4,%5,%6,%7}, {%8,%9}, {%0,%1,%2,%3};" \
        : "+f"((Cc)[0]), "+f"((Cc)[1]), "+f"((Cc)[2]), "+f"((Cc)[3]) \
        : "r"((A)[0]), "r"((A)[1]), "r"((A)[2]), "r"((A)[3]), "r"((B)[0]), "r"((B)[1]))

// ---------------- prep: sim col norms + logit scale + zero counters ----------------
__global__ void prec_kernel(const float* __restrict__ sim, const float* __restrict__ temp,
                            int C, int E) {
    int w = threadIdx.x >> 5, lane = threadIdx.x & 31;
    if (w < E) {
        float s = 0.f;
        for (int c = lane; c < C; c += 32) { float v = sim[(size_t)c * E + w]; s += v * v; }
        #pragma unroll
        for (int o = 16; o > 0; o >>= 1) s += __shfl_xor_sync(0xffffffffu, s, o);
        if (lane == 0) g_prec[w] = 1.f / fmaxf(sqrtf(s), L2_EPS);
    }
    if (threadIdx.x == 0) g_prec[MAX_E] = 1.f / (1.f + expf(-temp[0]));
    if (threadIdx.x < MAX_E) g_cnt[threadIdx.x] = 0;
}

// ---------------- gating (exact fp32) + fused compaction ----------------
__global__ void gating_kernel(const float* __restrict__ h, const float* __restrict__ sim,
                              const float* __restrict__ gates, const float* __restrict__ mask,
                              const int* __restrict__ min_experts_p,
                              float* __restrict__ out_logits, float* __restrict__ out_act,
                              int C, int E) {
    const int n = blockIdx.x, tid = threadIdx.x;
    float hh = 0.f;
    float dot[MAX_E];
    #pragma unroll
    for (int e = 0; e < MAX_E; e++) dot[e] = 0.f;
    const float* hrow = h + (size_t)n * C;
    for (int c = tid; c < C; c += 128) {
        float v = hrow[c];
        hh += v * v;
        const float* srow = sim + (size_t)c * E;
        #pragma unroll
        for (int e = 0; e < MAX_E; e++) if (e < E) dot[e] += v * srow[e];
    }
    __shared__ float sd[(MAX_E + 1) * 128];
    sd[tid] = hh;
    #pragma unroll
    for (int e = 0; e < MAX_E; e++) if (e < E) sd[(e + 1) * 128 + tid] = dot[e];
    __syncthreads();
    for (int s = 64; s > 0; s >>= 1) {
        if (tid < s)
            for (int r = 0; r <= E; r++) sd[r * 128 + tid] += sd[r * 128 + tid + s];
        __syncthreads();
    }
    if (tid == 0) {
        float inv_h = 1.f / fmaxf(sqrtf(sd[0]), L2_EPS);
        float ls = g_prec[MAX_E];
        float logits[MAX_E], act[MAX_E];
        float suma = 0.f;
        for (int e = 0; e < E; e++) {
            float lg = sd[(e + 1) * 128] * inv_h * g_prec[e];
            lg *= mask[e];
            logits[e] = lg;
            float gated = lg - gates[e] * ls;
            float a = (gated > 0.f) ? 1.f : 0.f;
            act[e] = a; suma += a;
        }
        if (suma == 0.f) {
            int k = min_experts_p ? *min_experts_p : 2;
            if (k <= 0 || k > E) {
                float f = __int_as_float(k);
                int k2 = (int)f;
                k = (k2 > 0 && k2 <= E) ? k2 : 2;
            }
            bool chosen[MAX_E];
            for (int e = 0; e < E; e++) chosen[e] = false;
            for (int j = 0; j < k; j++) {
                int best = -1; float bv = -1e30f;
                for (int e = 0; e < E; e++)
                    if (!chosen[e] && logits[e] > bv) { bv = logits[e]; best = e; }
                if (best >= 0) { chosen[best] = true; act[best] = 1.f; suma += 1.f; }
            }
        }
        float num = fmaxf(suma, 1.f);
        for (int e = 0; e < E; e++) {
            out_logits[(size_t)n * E + e] = logits[e];
            out_act[(size_t)n * E + e] = act[e];
            float sc = act[e] / num;
            g_scale[(size_t)n * E + e] = sc;
            if (sc != 0.f) {                       // fused compaction
                int slot = atomicAdd(&g_cnt[e], 1);
                g_tok[(size_t)e * MAX_N + slot] = n;
                g_pos[(size_t)n * E + e] = slot;
            }
        }
    }
}

// ---------------- fused prep: H -> fp16; W1, W2 -> transposed fp16 ----------------
__global__ void prep_kernel(const float* __restrict__ h,
                            const float* __restrict__ w1, const float* __restrict__ w2,
                            int N, int C, int I, int nb_h, int nb_w1) {
    __shared__ float t[32][33];
    const int bid = blockIdx.x;
    const int tid = threadIdx.x;

    if (bid < nb_h) {
        int i4 = bid * 256 + tid;
        float4 v = ((const float4*)h)[i4];
        __half h0 = __float2half_rn(v.x), h1 = __float2half_rn(v.y);
        __half h2 = __float2half_rn(v.z), h3 = __float2half_rn(v.w);
        uint2 hp;
        hp.x = (uint32_t)__half_as_ushort(h0) | ((uint32_t)__half_as_ushort(h1) << 16);
        hp.y = (uint32_t)__half_as_ushort(h2) | ((uint32_t)__half_as_ushort(h3) << 16);
        ((uint2*)g_h_h)[i4] = hp;
        return;
    }

    const float* src;
    __half* oh;
    int R, Cc, bx, by, e;
    if (bid < nb_h + nb_w1) {
        int b = bid - nb_h;
        R = C; Cc = I;                       // w1: [C][I] per expert
        int per_e = (Cc / 32) * (R / 32);
        e = b / per_e;
        int rem = b % per_e;
        bx = rem % (Cc / 32); by = rem / (Cc / 32);
        src = w1 + (size_t)e * R * Cc;
        oh = g_w1t + (size_t)e * R * Cc;
    } else {
        int b = bid - nb_h - nb_w1;
        R = I; Cc = C;                       // w2: [I][C] per expert
        int per_e = (Cc / 32) * (R / 32);
        e = b / per_e;
        int rem = b % per_e;
        bx = rem % (Cc / 32); by = rem / (Cc / 32);
        src = w2 + (size_t)e * R * Cc;
        oh = g_w2t + (size_t)e * R * Cc;
    }
    const int tx = tid & 31, ty = tid >> 5;  // (32, 8)
    int cbase = bx * 32, rbase = by * 32;
    #pragma unroll
    for (int i = 0; i < 4; i++) {
        int r = rbase + ty + i * 8;
        t[ty + i * 8][tx] = src[(size_t)r * Cc + cbase + tx];
    }
    __syncthreads();
    #pragma unroll
    for (int i = 0; i < 4; i++) {
        int n = cbase + ty + i * 8;
        int k = rbase + tx;
        oh[(size_t)n * R + k] = __float2half_rn(t[tx][ty + i * 8]);
    }
}

// ---------------- HMMA fp16 GEMM, CTA 128x128, 8 warps of 64x32, BK=64 ----------------
// 256 threads/CTA, acc 64 regs -> ~110 total -> 2 CTAs/SM = 16 warps/SM.
// 2-stage double buffer (36864 B/stage) + 512 B token cache = 74240 B/CTA.
// MODE 0: inter[e][slot] = gelu(H[tok[e][slot]] @ W1t[e]^T)  K=C, ncols=I (A gathered)
// MODE 1: out[token]    += scale * (inter[e][slot] @ W2t[e]^T)  (RED epilogue)
static constexpr int PITCH = 144;                        // 128 B row + 16 B pad
static constexpr int TILE_BYTES = 128 * PITCH;           // 18432
static constexpr int STAGE_BYTES = 2 * TILE_BYTES;       // 36864
static constexpr int SMEM_GEMM = 2 * STAGE_BYTES + 512;  // 74240

template <int MODE>
__global__ __launch_bounds__(256, 2)
void mma_gemm(int K, int ncols, float* __restrict__ out) {
    extern __shared__ __align__(128) char smem[];
    const int tid = threadIdx.x;
    const int wid = tid >> 5, lane = tid & 31;
    const int e = blockIdx.z;
    const int m0 = blockIdx.y * 128, n0 = blockIdx.x * 128;
    const int wm = wid & 1;          // M half (64 rows)
    const int wn = wid >> 1;         // 0..3 -> 32-col block

    const int cnt = g_cnt[e];
    if (m0 >= cnt) return;

    const __half* A = (MODE == 0) ? g_h_h : g_inter_h + (size_t)e * MAX_N * MAX_I;
    const __half* B = ((MODE == 0) ? g_w1t : g_w2t) + (size_t)e * ncols * K + (size_t)n0 * K;
    const int* tk = g_tok + (size_t)e * MAX_N;

    int* stok = (int*)(smem + 2 * STAGE_BYTES);   // cached A row indices
    if (tid < 128) {
        int r = min(m0 + tid, cnt - 1);
        stok[tid] = (MODE == 0) ? tk[r] : r;
    }
    __syncthreads();

    // Copy plan: 128 rows x 8 chunks(16B) per tile; 256 threads -> 4 tasks each
    const int r4 = tid >> 3;         // 0..31
    const int c16 = tid & 7;

    const uint32_t sb = smem_to_u32(smem);

    auto load_stage = [&](int buf, int k0) {
        uint32_t base = sb + (uint32_t)buf * (uint32_t)STAGE_BYTES;
        #pragma unroll
        for (int i = 0; i < 4; i++) {
            int row = r4 + 32 * i;
            int arow = stok[row];
            uint32_t soff = (uint32_t)row * (uint32_t)PITCH + (uint32_t)c16 * 16u;
            CP_ASYNC16(base + soff,                         A + (size_t)arow * K + k0 + c16 * 8);
            CP_ASYNC16(base + (uint32_t)TILE_BYTES + soff,  B + (size_t)row * K + k0 + c16 * 8);
        }
        CP_COMMIT();
    };

    const int NC = K >> 6;   // K=1024 -> 16, K=2048 -> 32
    load_stage(0, 0);
    load_stage(1, 64);

    float acc[4][4][4];
    #pragma unroll
    for (int a = 0; a < 4; a++)
        #pragma unroll
        for (int b = 0; b < 4; b++)
            #pragma unroll
            for (int d = 0; d < 4; d++) acc[a][b][d] = 0.f;

    for (int c = 0; c < NC; c++) {
        if (c == NC - 1) { CP_WAIT0(); } else { CP_WAIT1(); }
        __syncthreads();
        uint32_t base = sb + (uint32_t)(c & 1) * (uint32_t)STAGE_BYTES;

        #pragma unroll
        for (int ks = 0; ks < 4; ks++) {
            uint32_t Af[4][4];
            int arow = wm * 64 + (lane & 15);
            int acolb = (ks * 16 + (lane >> 4) * 8) * 2;
            #pragma unroll
            for (int mt = 0; mt < 4; mt++) {
                uint32_t ad = base + (uint32_t)(arow + mt * 16) * (uint32_t)PITCH + (uint32_t)acolb;
                LDSM4(Af[mt], ad);
            }
            // B: 32 cols = 4 nt blocks; two nt per packed LDSM4 -> 2 LDSM4 per ks.
            int brow = wn * 32 + (lane & 7) + (((lane >> 4) & 1) << 3);
            int bkb = (ks * 16 + ((lane >> 3) & 1) * 8) * 2;
            #pragma unroll
            for (int nt4 = 0; nt4 < 2; nt4++) {
                uint32_t Bp[4];
                uint32_t bd = base + (uint32_t)TILE_BYTES +
                              (uint32_t)(brow + nt4 * 16) * (uint32_t)PITCH + (uint32_t)bkb;
                LDSM4(Bp, bd);
                #pragma unroll
                for (int mt = 0; mt < 4; mt++) {
                    MMA16816F16(acc[mt][2 * nt4],     Af[mt], (&Bp[0]));
                    MMA16816F16(acc[mt][2 * nt4 + 1], Af[mt], (&Bp[2]));
                }
            }
        }
        __syncthreads();
        if (c + 2 < NC) load_stage(c & 1, (c + 2) * 64);
    }

    // ---------------- epilogue ----------------
    const int gq = lane >> 2, t2 = (lane & 3) * 2;
    if (MODE == 0) {
        __half* oh = g_inter_h + (size_t)e * MAX_N * MAX_I;
        #pragma unroll
        for (int mt = 0; mt < 4; mt++) {
            #pragma unroll
            for (int nt = 0; nt < 4; nt++) {
                int col = n0 + wn * 32 + nt * 8 + t2;
                #pragma unroll
                for (int hf = 0; hf < 2; hf++) {
                    int row = m0 + wm * 64 + mt * 16 + gq + hf * 8;
                    if (row >= cnt) continue;
                    float x0 = acc[mt][nt][2 * hf];
                    float x1 = acc[mt][nt][2 * hf + 1];
                    float g0 = 0.5f * x0 * (1.f + erff(x0 * 0.70710678118654752f));
                    float g1 = 0.5f * x1 * (1.f + erff(x1 * 0.70710678118654752f));
                    __half h0 = __float2half_rn(g0);
                    __half h1 = __float2half_rn(g1);
                    uint32_t hp = (uint32_t)__half_as_ushort(h0) |
                                  ((uint32_t)__half_as_ushort(h1) << 16);
                    *(uint32_t*)(oh + (size_t)row * ncols + col) = hp;
                }
            }
        }
    } else {
        // Fused scatter-reduce: out[token] += scale * acc  (RED, no return)
        #pragma unroll
        for (int mt = 0; mt < 4; mt++) {
            #pragma unroll
            for (int hf = 0; hf < 2; hf++) {
                int row = m0 + wm * 64 + mt * 16 + gq + hf * 8;
                if (row >= cnt) continue;
                int token = tk[row];
                float sc = g_scale[(size_t)token * MAX_E + e];
                float* orow = out + (size_t)token * ncols;
                #pragma unroll
                for (int nt = 0; nt < 4; nt++) {
                    int col = n0 + wn * 32 + nt * 8 + t2;
                    atomicAdd(&orow[col],     sc * acc[mt][nt][2 * hf]);
                    atomicAdd(&orow[col + 1], sc * acc[mt][nt][2 * hf + 1]);
                }
            }
        }
    }
}

// ---------------- launch ----------------
extern "C" void kernel_launch(void* const* d_in, const int* in_sizes, int n_in,
                              void* d_out, int out_size) {
    const float* h     = (const float*)d_in[0];
    const float* sim   = (const float*)d_in[1];
    const float* gates = (const float*)d_in[2];
    const float* temp  = (const float*)d_in[3];
    const float* mask  = (const float*)d_in[4];
    const float* w1    = (const float*)d_in[5];
    const float* w2    = (const float*)d_in[6];
    const int*   mi    = (const int*)d_in[7];

    const int E = in_sizes[2];
    const int C = in_sizes[1] / E;
    const int I = in_sizes[5] / (E * C);
    const int N = in_sizes[0] / C;

    float* out_final  = (float*)d_out;
    float* out_logits = out_final + (size_t)N * C;
    float* out_act    = out_logits + (size_t)N * E;

    cudaFuncSetAttribute(mma_gemm<0>, cudaFuncAttributeMaxDynamicSharedMemorySize, SMEM_GEMM);
    cudaFuncSetAttribute(mma_gemm<1>, cudaFuncAttributeMaxDynamicSharedMemorySize, SMEM_GEMM);

    cudaMemsetAsync(out_final, 0, (size_t)N * C * sizeof(float));
    prec_kernel<<<1, 256>>>(sim, temp, C, E);
    gating_kernel<<<N, 128>>>(h, sim, gates, mask, mi, out_logits, out_act, C, E);

    int nb_h  = (N * C) / 1024;            // split_h blocks (256 thr x 4 elems)
    int nb_w1 = E * (C / 32) * (I / 32);
    int nb_w2 = E * (I / 32) * (C / 32);
    prep_kernel<<<nb_h + nb_w1 + nb_w2, 256>>>(h, w1, w2, N, C, I, nb_h, nb_w1);

    mma_gemm<0><<<dim3(I / 128, N / 128, E), 256, SMEM_GEMM>>>(C, I, nullptr);
    mma_gemm<1><<<dim3(C / 128, N / 128, E), 256, SMEM_GEMM>>>(I, C, out_final);
}